// round 12
// baseline (speedup 1.0000x reference)
#include <cuda_runtime.h>
#include <cstdint>

#define B_   2
#define TQ_  2048
#define TKV_ 2048
#define DM_  1024
#define NH_  16
#define DH_  64
#define OUT_ELEMS (B_*TQ_*DM_)
#define ATT_ELEMS (B_*NH_*TQ_*TKV_)
#define SCALE_ 0.125f

__device__ float g_Q[B_*TQ_*DM_];
__device__ float g_K[B_*TKV_*DH_];
__device__ float g_VT[B_*DH_*TKV_];       // V transposed: [B][64][TKV]
__device__ float g_S[ATT_ELEMS];          // fallback attn dest only
__device__ float g_ATT[B_*TQ_*DM_];
__device__ float g_INV[B_*NH_*TQ_];       // per-row 1/rowsum

__device__ __forceinline__ uint32_t f2tf32(float f) {
    uint32_t u;
    asm("cvt.rna.tf32.f32 %0, %1;" : "=r"(u) : "f"(f));
    return u;
}
__device__ __forceinline__ uint32_t cvt_u(uint32_t w) {
    return f2tf32(__uint_as_float(w));
}
__device__ __forceinline__ uint32_t smaddr(const void* p) {
    return (uint32_t)__cvta_generic_to_shared(p);
}
__device__ __forceinline__ void cp16(uint32_t dst, const void* src) {
    asm volatile("cp.async.cg.shared.global [%0], [%1], 16;" :: "r"(dst), "l"(src));
}
__device__ __forceinline__ void cp_commit() {
    asm volatile("cp.async.commit_group;");
}
template<int N> __device__ __forceinline__ void cp_wait() {
    asm volatile("cp.async.wait_group %0;" :: "n"(N));
}
__device__ __forceinline__ void barg(int id) {
    asm volatile("bar.sync %0, %1;" :: "r"(id), "r"(256) : "memory");
}

__device__ __forceinline__ void mma_tf32(float c[4],
    uint32_t a0, uint32_t a1, uint32_t a2, uint32_t a3,
    uint32_t b0, uint32_t b1)
{
    asm volatile(
        "mma.sync.aligned.m16n8k8.row.col.f32.tf32.tf32.f32 "
        "{%0,%1,%2,%3},{%4,%5,%6,%7},{%8,%9},{%0,%1,%2,%3};"
        : "+f"(c[0]), "+f"(c[1]), "+f"(c[2]), "+f"(c[3])
        : "r"(a0), "r"(a1), "r"(a2), "r"(a3), "r"(b0), "r"(b1));
}

// ===================== pipelined TF32 GEMM core (3-stage cp.async) =====================
#define PK 36

// epi: 0 = plain fp32; 1 = tf32-round + K column pair-permute;
//      2 = tf32-round plain; 3 = tf32-round + transposed store (VT[n][kv])
template<int BN, int NTHR>
__device__ __forceinline__ void gemm_core(
    uint32_t* sm, const float* A, int lda, const float* Bp, int ldb,
    float* C, int ldc, const float* bias, int m0, int n0, int epi)
{
    const int STW = (128 + BN) * PK;
    const int tid = threadIdx.x;
    const int warpId = tid >> 5, lane = tid & 31;
    const int warpM = warpId & 1, warpN = warpId >> 1;
    const int g = lane >> 2, tg = lane & 3;

    constexpr int ACH = 1024 / NTHR;
    constexpr int BCH = (BN * 8) / NTHR;

    auto issue = [&](int t, int s) {
        const float* Asrc = A + (long long)m0 * lda + t * 32;
        uint32_t abase = smaddr(sm + s * STW);
        #pragma unroll
        for (int i = 0; i < ACH; i++) {
            int f = tid + i * NTHR;
            int row = f >> 3, c = f & 7;
            cp16(abase + (row * PK + c * 4) * 4, Asrc + (long long)row * lda + c * 4);
        }
        const float* Bsrc = Bp + (long long)n0 * ldb + t * 32;
        uint32_t bbase = smaddr(sm + s * STW + 128 * PK);
        #pragma unroll
        for (int i = 0; i < BCH; i++) {
            int f = tid + i * NTHR;
            int row = f >> 3, c = f & 7;
            cp16(bbase + (row * PK + c * 4) * 4, Bsrc + (long long)row * ldb + c * 4);
        }
        cp_commit();
    };

    float acc[4][4][4];
    #pragma unroll
    for (int mi = 0; mi < 4; mi++)
        #pragma unroll
        for (int ni = 0; ni < 4; ni++)
            #pragma unroll
            for (int r = 0; r < 4; r++) acc[mi][ni][r] = 0.f;

    const int T = 1024 / 32;
    issue(0, 0);
    issue(1, 1);

    for (int t = 0; t < T; t++) {
        if (t < T - 1) cp_wait<1>(); else cp_wait<0>();
        __syncthreads();
        if (t + 2 < T) issue(t + 2, (t + 2) % 3);

        const uint32_t* As = sm + (t % 3) * STW;
        const uint32_t* Bs = As + 128 * PK;

        #pragma unroll
        for (int kk = 0; kk < 32; kk += 8) {
            uint32_t a[4][4], b[4][2];
            #pragma unroll
            for (int mi = 0; mi < 4; mi++) {
                int mB = warpM * 64 + mi * 16;
                a[mi][0] = cvt_u(As[(mB + g    ) * PK + kk + tg    ]);
                a[mi][1] = cvt_u(As[(mB + g + 8) * PK + kk + tg    ]);
                a[mi][2] = cvt_u(As[(mB + g    ) * PK + kk + tg + 4]);
                a[mi][3] = cvt_u(As[(mB + g + 8) * PK + kk + tg + 4]);
            }
            #pragma unroll
            for (int ni = 0; ni < 4; ni++) {
                int nB = warpN * 32 + ni * 8;
                b[ni][0] = cvt_u(Bs[(nB + g) * PK + kk + tg    ]);
                b[ni][1] = cvt_u(Bs[(nB + g) * PK + kk + tg + 4]);
            }
            #pragma unroll
            for (int mi = 0; mi < 4; mi++)
                #pragma unroll
                for (int ni = 0; ni < 4; ni++)
                    mma_tf32(acc[mi][ni], a[mi][0], a[mi][1], a[mi][2], a[mi][3],
                             b[ni][0], b[ni][1]);
        }
    }

    #pragma unroll
    for (int mi = 0; mi < 4; mi++) {
        #pragma unroll
        for (int ni = 0; ni < 4; ni++) {
            int m = m0 + warpM * 64 + mi * 16 + g;
            int n = n0 + warpN * 32 + ni * 8 + 2 * tg;
            float b0 = bias[n], b1 = bias[n + 1];
            float v00 = acc[mi][ni][0] + b0, v01 = acc[mi][ni][1] + b1;
            float v10 = acc[mi][ni][2] + b0, v11 = acc[mi][ni][3] + b1;
            if (epi == 0) {
                *reinterpret_cast<float2*>(C + (long long)m * ldc + n)       = make_float2(v00, v01);
                *reinterpret_cast<float2*>(C + (long long)(m + 8) * ldc + n) = make_float2(v10, v11);
            } else {
                float r00 = __uint_as_float(f2tf32(v00));
                float r01 = __uint_as_float(f2tf32(v01));
                float r10 = __uint_as_float(f2tf32(v10));
                float r11 = __uint_as_float(f2tf32(v11));
                if (epi == 1) {
                    int base = n & ~7;
                    int j0 = n & 7, j1 = j0 + 1;
                    int n0p = base + ((j0 < 4) ? 2*j0 : 2*j0 - 7);
                    int n1p = base + ((j1 < 4) ? 2*j1 : 2*j1 - 7);
                    C[(long long)m * ldc + n0p] = r00;
                    C[(long long)m * ldc + n1p] = r01;
                    C[(long long)(m + 8) * ldc + n0p] = r10;
                    C[(long long)(m + 8) * ldc + n1p] = r11;
                } else if (epi == 3) {
                    long long bb  = (long long)(m >> 11) * DH_ * TKV_;
                    int kv0 = m & (TKV_ - 1);
                    C[bb + (long long)n       * TKV_ + kv0    ] = r00;
                    C[bb + (long long)(n + 1) * TKV_ + kv0    ] = r01;
                    C[bb + (long long)n       * TKV_ + kv0 + 8] = r10;
                    C[bb + (long long)(n + 1) * TKV_ + kv0 + 8] = r11;
                } else {
                    *reinterpret_cast<float2*>(C + (long long)m * ldc + n)       = make_float2(r00, r01);
                    *reinterpret_cast<float2*>(C + (long long)(m + 8) * ldc + n) = make_float2(r10, r11);
                }
            }
        }
    }
}

#define PROJ_SMEM ((3*(128+128)*PK)*4)
#define KVP_SMEM  ((3*(128+64)*PK)*4)

__global__ void __launch_bounds__(256, 2) proj_gemm(
    const float* __restrict__ A, const float* __restrict__ Bp,
    float* __restrict__ C, const float* __restrict__ bias, int epi)
{
    extern __shared__ uint32_t sm[];
    gemm_core<128, 256>(sm, A, DM_, Bp, DM_, C, DM_, bias,
                        blockIdx.y * 128, blockIdx.x * 128, epi);
}

__global__ void __launch_bounds__(128) kv_pipe(
    const float* __restrict__ A,
    const float* __restrict__ Wk_, const float* __restrict__ Wv_,
    const float* __restrict__ bk_, const float* __restrict__ bv_,
    float* __restrict__ CK, float* __restrict__ CVT)
{
    extern __shared__ uint32_t sm[];
    const float* Bp   = blockIdx.z ? Wv_ : Wk_;
    const float* bias = blockIdx.z ? bv_ : bk_;
    float* C          = blockIdx.z ? CVT : CK;
    gemm_core<64, 128>(sm, A, DM_, Bp, DM_, C, DH_, bias,
                       blockIdx.y * 128, 0, blockIdx.z ? 3 : 1);
}

// ===================== zero upper-triangle of P (fully off critical path) =====================
__global__ void __launch_bounds__(256) zero_P(float* __restrict__ P)
{
    const int m0 = blockIdx.x * 128;
    float* Pp = P + (long long)blockIdx.y * TQ_ * TKV_;
    const int zc0 = m0 + 128;
    const int W = (TKV_ - zc0) >> 2;
    if (W <= 0) return;
    float4 z = make_float4(0.f, 0.f, 0.f, 0.f);
    for (int idx = threadIdx.x; idx < 128 * W; idx += 256) {
        int r = idx / W, c4 = idx - r * W;
        *reinterpret_cast<float4*>(Pp + (long long)(m0 + r) * TKV_ + zc0 + c4*4) = z;
    }
}

// ===================== Fused attention =====================
#define KP2 72
#define VTP 136
#define KBW (128*KP2)
#define VTW (64*VTP)
#define FA_SMEM_BYTES ((3*KBW + 3*VTW)*4)   // 215040 B

__global__ void __launch_bounds__(512, 1) fused_attn(
    const float* __restrict__ Qg, const float* __restrict__ Kg,
    const float* __restrict__ VTg, float* __restrict__ Pg,
    float* __restrict__ Og, float* __restrict__ Invg)
{
    extern __shared__ uint32_t sm[];

    const int qb = gridDim.x - 1 - blockIdx.x;   // heavy blocks first
    const int m0 = qb * 128;
    const int bh = blockIdx.y;
    const int b  = bh >> 4, h = bh & 15;

    const float* Qp  = Qg  + (long long)b * TQ_ * DM_ + h * DH_;
    const float* Kp  = Kg  + (long long)b * TKV_ * DH_;
    const float* VTp = VTg + (long long)b * DH_ * TKV_;
    float* Pp = Pg + (long long)bh * TQ_ * TKV_;
    float* Op = Og + (long long)b * TQ_ * DM_ + h * DH_;

    const int tid = threadIdx.x;
    const int wid = tid >> 5;
    const int wr  = wid & 7;          // 16-row band
    const int grp = wid >> 3;         // group 0: kv cols [0,64); group 1: [64,128)
    const int wc  = grp * 64;
    const int ltid = tid & 255;
    const int lane = tid & 31;
    const int g = lane >> 2, tg = lane & 3;
    const int row0 = m0 + wr * 16 + g;

    auto issueHalf = [&](int t, int s) {
        uint32_t kb = smaddr(sm + s * KBW);
        uint32_t vb = smaddr(sm + 3 * KBW + s * VTW);
        #pragma unroll
        for (int i = 0; i < 4; i++) {
            int f = ltid + i * 256;
            int row = wc + (f >> 4), c = f & 15;
            cp16(kb + (row * KP2 + c * 4) * 4,
                 Kp + (long long)(t * 128 + row) * DH_ + c * 4);
        }
        #pragma unroll
        for (int i = 0; i < 4; i++) {
            int f = ltid + i * 256;
            int nrow = f >> 4;
            int ccol = wc + (f & 15) * 4;
            cp16(vb + (nrow * VTP + ccol) * 4,
                 VTp + (long long)nrow * TKV_ + t * 128 + ccol);
        }
        cp_commit();
    };

    // ---- stage Q (pre-rounded tf32 in gmem) via cp.async ----
    {
        uint32_t qbse = smaddr(sm);
        #pragma unroll
        for (int i = 0; i < 4; i++) {
            int f = tid + i * 512;
            int row = f >> 4, c = f & 15;
            cp16(qbse + (row * KP2 + c * 4) * 4,
                 Qp + (long long)(m0 + row) * DM_ + c * 4);
        }
        cp_commit();
        cp_wait<0>();
    }
    __syncthreads();
    uint32_t qf[8][4];
    #pragma unroll
    for (int kc = 0; kc < 8; kc++) {
        qf[kc][0] = sm[(wr*16 + g    ) * KP2 + kc*8 + tg    ];
        qf[kc][1] = sm[(wr*16 + g + 8) * KP2 + kc*8 + tg    ];
        qf[kc][2] = sm[(wr*16 + g    ) * KP2 + kc*8 + tg + 4];
        qf[kc][3] = sm[(wr*16 + g + 8) * KP2 + kc*8 + tg + 4];
    }
    __syncthreads();

    const int nT = qb + 1;
    float rs0 = 0.f, rs1 = 0.f;
    float accO[8][4];
    #pragma unroll
    for (int nj = 0; nj < 8; nj++)
        #pragma unroll
        for (int r = 0; r < 4; r++) accO[nj][r] = 0.f;

    issueHalf(0, 0);
    if (nT > 1) issueHalf(1, 1);

    for (int t = 0; t < nT; t++) {
        if (t < nT - 1) cp_wait<1>(); else cp_wait<0>();
        barg(1 + grp);
        if (t + 2 < nT) issueHalf(t + 2, (t + 2) % 3);

        const int k0 = t * 128;
        const uint32_t* Ks = sm + (t % 3) * KBW;
        const uint32_t* Vs = sm + 3 * KBW + (t % 3) * VTW;
        const bool diag = (t == nT - 1);

        // Fully-masked warp band on the diagonal tile: write zeros, skip compute.
        if (diag && wc >= wr * 16 + 16) {
            float2 z2 = make_float2(0.f, 0.f);
            #pragma unroll
            for (int ni = 0; ni < 8; ni++) {
                int col = k0 + wc + ni*8 + 2*tg;
                *reinterpret_cast<float2*>(Pp + (long long)row0       * TKV_ + col) = z2;
                *reinterpret_cast<float2*>(Pp + (long long)(row0 + 8) * TKV_ + col) = z2;
            }
            continue;
        }

        // --- QK^T over this group's 64 kv cols ---
        float accS[8][4];
        #pragma unroll
        for (int ni = 0; ni < 8; ni++)
            #pragma unroll
            for (int r = 0; r < 4; r++) accS[ni][r] = 0.f;
        #pragma unroll
        for (int kc = 0; kc < 8; kc++) {
            uint2 bp[8];
            #pragma unroll
            for (int ni = 0; ni < 8; ni++)
                bp[ni] = *reinterpret_cast<const uint2*>(
                    &Ks[(wc + ni*8 + g) * KP2 + kc*8 + 2*tg]);
            #pragma unroll
            for (int ni = 0; ni < 8; ni++)
                mma_tf32(accS[ni], qf[kc][0], qf[kc][1], qf[kc][2], qf[kc][3],
                         bp[ni].x, bp[ni].y);
        }

        // --- E = exp(s/8), causal mask on diag tile, write unnormalized ---
        #pragma unroll
        for (int ni = 0; ni < 8; ni++) {
            int col = k0 + wc + ni*8 + 2*tg;
            float p0 = __expf(accS[ni][0]*SCALE_);
            float p1 = __expf(accS[ni][1]*SCALE_);
            float p2 = __expf(accS[ni][2]*SCALE_);
            float p3 = __expf(accS[ni][3]*SCALE_);
            if (diag) {
                if (col     > row0    ) p0 = 0.f;
                if (col + 1 > row0    ) p1 = 0.f;
                if (col     > row0 + 8) p2 = 0.f;
                if (col + 1 > row0 + 8) p3 = 0.f;
            }
            rs0 += p0 + p1;
            rs1 += p2 + p3;
            *reinterpret_cast<float2*>(Pp + (long long)row0       * TKV_ + col) = make_float2(p0, p1);
            *reinterpret_cast<float2*>(Pp + (long long)(row0 + 8) * TKV_ + col) = make_float2(p2, p3);
            accS[ni][0] = p0; accS[ni][1] = p1; accS[ni][2] = p2; accS[ni][3] = p3;
        }

        // --- AV: a-frag = (c0,c2,c1,c3); VT b-frag = one LDS.64 ---
        #pragma unroll
        for (int kc = 0; kc < 8; kc++) {
            uint32_t af0 = f2tf32(accS[kc][0]);
            uint32_t af1 = f2tf32(accS[kc][2]);
            uint32_t af2 = f2tf32(accS[kc][1]);
            uint32_t af3 = f2tf32(accS[kc][3]);
            #pragma unroll
            for (int nj = 0; nj < 8; nj++) {
                uint2 bv = *reinterpret_cast<const uint2*>(
                    &Vs[(nj*8 + g) * VTP + wc + kc*8 + 2*tg]);
                mma_tf32(accO[nj], af0, af1, af2, af3, bv.x, bv.y);
            }
        }
    }

    // ---- cross-group reduction (rowsum + partial O) ----
    rs0 += __shfl_xor_sync(0xffffffffu, rs0, 1);
    rs0 += __shfl_xor_sync(0xffffffffu, rs0, 2);
    rs1 += __shfl_xor_sync(0xffffffffu, rs1, 1);
    rs1 += __shfl_xor_sync(0xffffffffu, rs1, 2);

    __syncthreads();
    float* redS = (float*)sm;              // [8][32] rowsums
    float* redO = (float*)sm + 256;        // [8][32][32] partial O
    if (grp == 1) {
        if (tg == 0) {
            redS[wr * 32 + g]      = rs0;
            redS[wr * 32 + 16 + g] = rs1;
        }
        #pragma unroll
        for (int nj = 0; nj < 8; nj++)
            #pragma unroll
            for (int r = 0; r < 4; r++)
                redO[(wr * 32 + lane) * 32 + nj * 4 + r] = accO[nj][r];
    }
    __syncthreads();

    if (grp == 0) {
        rs0 += redS[wr * 32 + g];
        rs1 += redS[wr * 32 + 16 + g];
        const float inv0 = 1.0f / rs0;
        const float inv1 = 1.0f / rs1;
        if (tg == 0) {
            Invg[(long long)bh * TQ_ + row0]     = inv0;
            Invg[(long long)bh * TQ_ + row0 + 8] = inv1;
        }
        #pragma unroll
        for (int nj = 0; nj < 8; nj++) {
            float o0 = accO[nj][0] + redO[(wr * 32 + lane) * 32 + nj * 4 + 0];
            float o1 = accO[nj][1] + redO[(wr * 32 + lane) * 32 + nj * 4 + 1];
            float o2 = accO[nj][2] + redO[(wr * 32 + lane) * 32 + nj * 4 + 2];
            float o3 = accO[nj][3] + redO[(wr * 32 + lane) * 32 + nj * 4 + 3];
            int col = nj*8 + 2*tg;
            *reinterpret_cast<float2*>(Op + (long long)row0       * DM_ + col) =
                make_float2(o0 * inv0, o1 * inv0);
            *reinterpret_cast<float2*>(Op + (long long)(row0 + 8) * DM_ + col) =
                make_float2(o2 * inv1, o3 * inv1);
        }
    }
}

// ===================== normalize P (causal half only) =====================
__global__ void __launch_bounds__(128) normalize_P(
    float* __restrict__ P, const float* __restrict__ Inv)
{
    const long long r = blockIdx.x;
    const int q = (int)(r & (TQ_ - 1));
    const float s = Inv[r];
    float4* p = reinterpret_cast<float4*>(P + r * TKV_);
    const int n4 = (q + 4) >> 2;
    for (int i = threadIdx.x; i < n4; i += 128) {
        float4 v = p[i];
        v.x *= s; v.y *= s; v.z *= s; v.w *= s;
        p[i] = v;
    }
}

// ===================== launch =====================
extern "C" void kernel_launch(void* const* d_in, const int* in_sizes, int n_in,
                              void* d_out, int out_size)
{
    const float* q  = (const float*)d_in[0];
    const float* kv = (const float*)d_in[1];
    const float* Wq = (const float*)d_in[3];
    const float* bq = (const float*)d_in[4];
    const float* Wk = (const float*)d_in[5];
    const float* bk = (const float*)d_in[6];
    const float* Wv = (const float*)d_in[7];
    const float* bv = (const float*)d_in[8];
    const float* Wo = (const float*)d_in[9];
    const float* bo = (const float*)d_in[10];
    float* out = (float*)d_out;
    (void)in_sizes; (void)n_in;

    float *gQ, *gK, *gVT, *gS, *gATT, *gINV;
    cudaGetSymbolAddress((void**)&gQ,   g_Q);
    cudaGetSymbolAddress((void**)&gK,   g_K);
    cudaGetSymbolAddress((void**)&gVT,  g_VT);
    cudaGetSymbolAddress((void**)&gS,   g_S);
    cudaGetSymbolAddress((void**)&gATT, g_ATT);
    cudaGetSymbolAddress((void**)&gINV, g_INV);

    float* attn_dst = (out_size >= OUT_ELEMS + ATT_ELEMS) ? (out + OUT_ELEMS) : gS;

    static cudaStream_t s1 = nullptr, s2 = nullptr;
    static cudaEvent_t e0 = nullptr, e1 = nullptr, e2 = nullptr, e3 = nullptr, ez = nullptr;
    static bool init_done = false;
    if (!init_done) {
        cudaFuncSetAttribute(proj_gemm,
            cudaFuncAttributeMaxDynamicSharedMemorySize, PROJ_SMEM);
        cudaFuncSetAttribute(kv_pipe,
            cudaFuncAttributeMaxDynamicSharedMemorySize, KVP_SMEM);
        cudaFuncSetAttribute(fused_attn,
            cudaFuncAttributeMaxDynamicSharedMemorySize, FA_SMEM_BYTES);
        cudaStreamCreateWithFlags(&s1, cudaStreamNonBlocking);
        cudaStreamCreateWithFlags(&s2, cudaStreamNonBlocking);
        cudaEventCreateWithFlags(&e0, cudaEventDisableTiming);
        cudaEventCreateWithFlags(&e1, cudaEventDisableTiming);
        cudaEventCreateWithFlags(&e2, cudaEventDisableTiming);
        cudaEventCreateWithFlags(&e3, cudaEventDisableTiming);
        cudaEventCreateWithFlags(&ez, cudaEventDisableTiming);
        init_done = true;
    }

    // fork: kv proj on s1, zero-fill on s2, Q proj on main
    cudaEventRecord(e0, 0);
    cudaStreamWaitEvent(s1, e0, 0);
    cudaStreamWaitEvent(s2, e0, 0);
    kv_pipe<<<dim3(1, (B_*TKV_)/128, 2), 128, KVP_SMEM, s1>>>(
        kv, Wk, Wv, bk, bv, gK, gVT);
    cudaEventRecord(e1, s1);
    zero_P<<<dim3(TQ_/128, B_*NH_), 256, 0, s2>>>(attn_dst);
    cudaEventRecord(ez, s2);

    proj_gemm<<<dim3(DM_/128, (B_*TQ_)/128), 256, PROJ_SMEM>>>(q, Wq, gQ, bq, 2);

    // join kv, then fused attention on main
    cudaStreamWaitEvent(0, e1, 0);
    fused_attn<<<dim3(TQ_/128, B_*NH_), 512, FA_SMEM_BYTES>>>(
        gQ, gK, gVT, attn_dst, gATT, gINV);

    // fork: normalize on s1 overlaps final projection on main
    cudaEventRecord(e2, 0);
    cudaStreamWaitEvent(s1, e2, 0);
    normalize_P<<<B_*NH_*TQ_, 128, 0, s1>>>(attn_dst, gINV);
    cudaEventRecord(e3, s1);

    proj_gemm<<<dim3(DM_/128, (B_*TQ_)/128), 256, PROJ_SMEM>>>(gATT, Wo, out, bo, 0);
    cudaStreamWaitEvent(0, e3, 0);
    cudaStreamWaitEvent(0, ez, 0);
}

// round 13
// speedup vs baseline: 1.0726x; 1.0726x over previous
#include <cuda_runtime.h>
#include <cstdint>

#define B_   2
#define TQ_  2048
#define TKV_ 2048
#define DM_  1024
#define NH_  16
#define DH_  64
#define OUT_ELEMS (B_*TQ_*DM_)
#define ATT_ELEMS (B_*NH_*TQ_*TKV_)
#define SC2_ 0.18033688011112543f   /* 0.125 * log2(e) */

__device__ float g_Q[B_*TQ_*DM_];
__device__ float g_K[B_*TKV_*DH_];
__device__ float g_VT[B_*DH_*TKV_];
__device__ float g_S[ATT_ELEMS];
__device__ float g_ATT[B_*TQ_*DM_];
__device__ float g_INV[B_*NH_*TQ_];

__device__ __forceinline__ uint32_t f2tf32(float f) {
    uint32_t u;
    asm("cvt.rna.tf32.f32 %0, %1;" : "=r"(u) : "f"(f));
    return u;
}
__device__ __forceinline__ uint32_t cvt_u(uint32_t w) {
    return f2tf32(__uint_as_float(w));
}
__device__ __forceinline__ uint32_t smaddr(const void* p) {
    return (uint32_t)__cvta_generic_to_shared(p);
}
__device__ __forceinline__ void cp16(uint32_t dst, const void* src) {
    asm volatile("cp.async.cg.shared.global [%0], [%1], 16;" :: "r"(dst), "l"(src));
}
__device__ __forceinline__ void cp_commit() {
    asm volatile("cp.async.commit_group;");
}
template<int N> __device__ __forceinline__ void cp_wait() {
    asm volatile("cp.async.wait_group %0;" :: "n"(N));
}
__device__ __forceinline__ void barg128(int id) {
    asm volatile("bar.sync %0, %1;" :: "r"(id), "r"(128) : "memory");
}

__device__ __forceinline__ void mma_tf32(float c[4],
    uint32_t a0, uint32_t a1, uint32_t a2, uint32_t a3,
    uint32_t b0, uint32_t b1)
{
    asm volatile(
        "mma.sync.aligned.m16n8k8.row.col.f32.tf32.tf32.f32 "
        "{%0,%1,%2,%3},{%4,%5,%6,%7},{%8,%9},{%0,%1,%2,%3};"
        : "+f"(c[0]), "+f"(c[1]), "+f"(c[2]), "+f"(c[3])
        : "r"(a0), "r"(a1), "r"(a2), "r"(a3), "r"(b0), "r"(b1));
}

// ===================== pipelined TF32 GEMM core (3-stage cp.async) =====================
#define PK 36

template<int BN, int NTHR>
__device__ __forceinline__ void gemm_core(
    uint32_t* sm, const float* A, int lda, const float* Bp, int ldb,
    float* C, int ldc, const float* bias, int m0, int n0, int epi)
{
    const int STW = (128 + BN) * PK;
    const int tid = threadIdx.x;
    const int warpId = tid >> 5, lane = tid & 31;
    const int warpM = warpId & 1, warpN = warpId >> 1;
    const int g = lane >> 2, tg = lane & 3;

    constexpr int ACH = 1024 / NTHR;
    constexpr int BCH = (BN * 8) / NTHR;

    auto issue = [&](int t, int s) {
        const float* Asrc = A + (long long)m0 * lda + t * 32;
        uint32_t abase = smaddr(sm + s * STW);
        #pragma unroll
        for (int i = 0; i < ACH; i++) {
            int f = tid + i * NTHR;
            int row = f >> 3, c = f & 7;
            cp16(abase + (row * PK + c * 4) * 4, Asrc + (long long)row * lda + c * 4);
        }
        const float* Bsrc = Bp + (long long)n0 * ldb + t * 32;
        uint32_t bbase = smaddr(sm + s * STW + 128 * PK);
        #pragma unroll
        for (int i = 0; i < BCH; i++) {
            int f = tid + i * NTHR;
            int row = f >> 3, c = f & 7;
            cp16(bbase + (row * PK + c * 4) * 4, Bsrc + (long long)row * ldb + c * 4);
        }
        cp_commit();
    };

    float acc[4][4][4];
    #pragma unroll
    for (int mi = 0; mi < 4; mi++)
        #pragma unroll
        for (int ni = 0; ni < 4; ni++)
            #pragma unroll
            for (int r = 0; r < 4; r++) acc[mi][ni][r] = 0.f;

    const int T = 1024 / 32;
    issue(0, 0);
    issue(1, 1);

    for (int t = 0; t < T; t++) {
        if (t < T - 1) cp_wait<1>(); else cp_wait<0>();
        __syncthreads();
        if (t + 2 < T) issue(t + 2, (t + 2) % 3);

        const uint32_t* As = sm + (t % 3) * STW;
        const uint32_t* Bs = As + 128 * PK;

        #pragma unroll
        for (int kk = 0; kk < 32; kk += 8) {
            uint32_t a[4][4], b[4][2];
            #pragma unroll
            for (int mi = 0; mi < 4; mi++) {
                int mB = warpM * 64 + mi * 16;
                a[mi][0] = cvt_u(As[(mB + g    ) * PK + kk + tg    ]);
                a[mi][1] = cvt_u(As[(mB + g + 8) * PK + kk + tg    ]);
                a[mi][2] = cvt_u(As[(mB + g    ) * PK + kk + tg + 4]);
                a[mi][3] = cvt_u(As[(mB + g + 8) * PK + kk + tg + 4]);
            }
            #pragma unroll
            for (int ni = 0; ni < 4; ni++) {
                int nB = warpN * 32 + ni * 8;
                b[ni][0] = cvt_u(Bs[(nB + g) * PK + kk + tg    ]);
                b[ni][1] = cvt_u(Bs[(nB + g) * PK + kk + tg + 4]);
            }
            #pragma unroll
            for (int mi = 0; mi < 4; mi++)
                #pragma unroll
                for (int ni = 0; ni < 4; ni++)
                    mma_tf32(acc[mi][ni], a[mi][0], a[mi][1], a[mi][2], a[mi][3],
                             b[ni][0], b[ni][1]);
        }
    }

    #pragma unroll
    for (int mi = 0; mi < 4; mi++) {
        #pragma unroll
        for (int ni = 0; ni < 4; ni++) {
            int m = m0 + warpM * 64 + mi * 16 + g;
            int n = n0 + warpN * 32 + ni * 8 + 2 * tg;
            float b0 = bias[n], b1 = bias[n + 1];
            float v00 = acc[mi][ni][0] + b0, v01 = acc[mi][ni][1] + b1;
            float v10 = acc[mi][ni][2] + b0, v11 = acc[mi][ni][3] + b1;
            if (epi == 0) {
                *reinterpret_cast<float2*>(C + (long long)m * ldc + n)       = make_float2(v00, v01);
                *reinterpret_cast<float2*>(C + (long long)(m + 8) * ldc + n) = make_float2(v10, v11);
            } else {
                float r00 = __uint_as_float(f2tf32(v00));
                float r01 = __uint_as_float(f2tf32(v01));
                float r10 = __uint_as_float(f2tf32(v10));
                float r11 = __uint_as_float(f2tf32(v11));
                if (epi == 1) {
                    int base = n & ~7;
                    int j0 = n & 7, j1 = j0 + 1;
                    int n0p = base + ((j0 < 4) ? 2*j0 : 2*j0 - 7);
                    int n1p = base + ((j1 < 4) ? 2*j1 : 2*j1 - 7);
                    C[(long long)m * ldc + n0p] = r00;
                    C[(long long)m * ldc + n1p] = r01;
                    C[(long long)(m + 8) * ldc + n0p] = r10;
                    C[(long long)(m + 8) * ldc + n1p] = r11;
                } else if (epi == 3) {
                    long long bb  = (long long)(m >> 11) * DH_ * TKV_;
                    int kv0 = m & (TKV_ - 1);
                    C[bb + (long long)n       * TKV_ + kv0    ] = r00;
                    C[bb + (long long)(n + 1) * TKV_ + kv0    ] = r01;
                    C[bb + (long long)n       * TKV_ + kv0 + 8] = r10;
                    C[bb + (long long)(n + 1) * TKV_ + kv0 + 8] = r11;
                } else {
                    *reinterpret_cast<float2*>(C + (long long)m * ldc + n)       = make_float2(r00, r01);
                    *reinterpret_cast<float2*>(C + (long long)(m + 8) * ldc + n) = make_float2(r10, r11);
                }
            }
        }
    }
}

#define PROJ_SMEM ((3*(128+128)*PK)*4)
#define KVP_SMEM  ((3*(128+64)*PK)*4)

__global__ void __launch_bounds__(256, 2) proj_gemm(
    const float* __restrict__ A, const float* __restrict__ Bp,
    float* __restrict__ C, const float* __restrict__ bias, int epi)
{
    extern __shared__ uint32_t sm[];
    gemm_core<128, 256>(sm, A, DM_, Bp, DM_, C, DM_, bias,
                        blockIdx.y * 128, blockIdx.x * 128, epi);
}

__global__ void __launch_bounds__(128) kv_pipe(
    const float* __restrict__ A,
    const float* __restrict__ Wk_, const float* __restrict__ Wv_,
    const float* __restrict__ bk_, const float* __restrict__ bv_,
    float* __restrict__ CK, float* __restrict__ CVT)
{
    extern __shared__ uint32_t sm[];
    const float* Bp   = blockIdx.z ? Wv_ : Wk_;
    const float* bias = blockIdx.z ? bv_ : bk_;
    float* C          = blockIdx.z ? CVT : CK;
    gemm_core<64, 128>(sm, A, DM_, Bp, DM_, C, DH_, bias,
                       blockIdx.y * 128, 0, blockIdx.z ? 3 : 1);
}

// ===================== zero upper-triangle of P =====================
__global__ void __launch_bounds__(256) zero_P(float* __restrict__ P)
{
    const int m0 = blockIdx.x * 128;
    float* Pp = P + (long long)blockIdx.y * TQ_ * TKV_;
    const int zc0 = m0 + 128;
    const int W = (TKV_ - zc0) >> 2;
    if (W <= 0) return;
    float4 z = make_float4(0.f, 0.f, 0.f, 0.f);
    for (int idx = threadIdx.x; idx < 128 * W; idx += 256) {
        int r = idx / W, c4 = idx - r * W;
        *reinterpret_cast<float4*>(Pp + (long long)(m0 + r) * TKV_ + zc0 + c4*4) = z;
    }
}

// ===================== Fused attention: 8 warps, 32 q-rows/warp (b-frag reuse x2) =====================
#define KP2 72
#define VTP 136
#define KBW (128*KP2)
#define VTW (64*VTP)
#define FA_SMEM_BYTES ((3*KBW + 3*VTW)*4)   // 215040 B

__global__ void __launch_bounds__(256, 1) fused_attn(
    const float* __restrict__ Qg, const float* __restrict__ Kg,
    const float* __restrict__ VTg, float* __restrict__ Pg,
    float* __restrict__ Og, float* __restrict__ Invg)
{
    extern __shared__ uint32_t sm[];

    const int qb = gridDim.x - 1 - blockIdx.x;   // heavy blocks first
    const int m0 = qb * 128;
    const int bh = blockIdx.y;
    const int b  = bh >> 4, h = bh & 15;

    const float* Qp  = Qg  + (long long)b * TQ_ * DM_ + h * DH_;
    const float* Kp  = Kg  + (long long)b * TKV_ * DH_;
    const float* VTp = VTg + (long long)b * DH_ * TKV_;
    float* Pp = Pg + (long long)bh * TQ_ * TKV_;
    float* Op = Og + (long long)b * TQ_ * DM_ + h * DH_;

    const int tid = threadIdx.x;
    const int wid = tid >> 5;
    const int wr  = wid & 3;          // 32-row band
    const int grp = wid >> 2;         // kv half
    const int wc  = grp * 64;
    const int ltid = tid & 127;
    const int lane = tid & 31;
    const int g = lane >> 2, tg = lane & 3;

    auto issueHalf = [&](int t, int s) {
        uint32_t kb = smaddr(sm + s * KBW);
        uint32_t vb = smaddr(sm + 3 * KBW + s * VTW);
        #pragma unroll
        for (int i = 0; i < 8; i++) {
            int f = ltid + i * 128;
            int row = wc + (f >> 4), c = f & 15;
            cp16(kb + (row * KP2 + c * 4) * 4,
                 Kp + (long long)(t * 128 + row) * DH_ + c * 4);
        }
        #pragma unroll
        for (int i = 0; i < 8; i++) {
            int f = ltid + i * 128;
            int nrow = f >> 4;
            int ccol = wc + (f & 15) * 4;
            cp16(vb + (nrow * VTP + ccol) * 4,
                 VTp + (long long)nrow * TKV_ + t * 128 + ccol);
        }
        cp_commit();
    };

    // ---- stage Q (pre-rounded tf32) ----
    {
        uint32_t qbse = smaddr(sm);
        #pragma unroll
        for (int i = 0; i < 8; i++) {
            int f = tid + i * 256;
            int row = f >> 4, c = f & 15;
            cp16(qbse + (row * KP2 + c * 4) * 4,
                 Qp + (long long)(m0 + row) * DM_ + c * 4);
        }
        cp_commit();
        cp_wait<0>();
    }
    __syncthreads();
    uint32_t qf[8][2][4];
    #pragma unroll
    for (int kc = 0; kc < 8; kc++)
        #pragma unroll
        for (int mt = 0; mt < 2; mt++) {
            int rw = wr*32 + mt*16 + g;
            qf[kc][mt][0] = sm[(rw    ) * KP2 + kc*8 + tg    ];
            qf[kc][mt][1] = sm[(rw + 8) * KP2 + kc*8 + tg    ];
            qf[kc][mt][2] = sm[(rw    ) * KP2 + kc*8 + tg + 4];
            qf[kc][mt][3] = sm[(rw + 8) * KP2 + kc*8 + tg + 4];
        }
    __syncthreads();

    const int nT = qb + 1;
    float rs[2][2];
    rs[0][0] = rs[0][1] = rs[1][0] = rs[1][1] = 0.f;
    float accO[2][8][4];
    #pragma unroll
    for (int mt = 0; mt < 2; mt++)
        #pragma unroll
        for (int nj = 0; nj < 8; nj++)
            #pragma unroll
            for (int r = 0; r < 4; r++) accO[mt][nj][r] = 0.f;

    issueHalf(0, 0);
    if (nT > 1) issueHalf(1, 1);

    for (int t = 0; t < nT; t++) {
        if (t < nT - 1) cp_wait<1>(); else cp_wait<0>();
        barg128(1 + grp);
        if (t + 2 < nT) issueHalf(t + 2, (t + 2) % 3);

        const int k0 = t * 128;
        const uint32_t* Ks = sm + (t % 3) * KBW;
        const uint32_t* Vs = sm + 3 * KBW + (t % 3) * VTW;
        const bool diag = (t == nT - 1);

        // Fully-masked band: write zeros, skip compute.
        if (diag && wc >= wr * 32 + 32) {
            float2 z2 = make_float2(0.f, 0.f);
            #pragma unroll
            for (int mt = 0; mt < 2; mt++) {
                int rw = m0 + wr*32 + mt*16 + g;
                #pragma unroll
                for (int ni = 0; ni < 8; ni++) {
                    int col = k0 + wc + ni*8 + 2*tg;
                    *reinterpret_cast<float2*>(Pp + (long long)rw       * TKV_ + col) = z2;
                    *reinterpret_cast<float2*>(Pp + (long long)(rw + 8) * TKV_ + col) = z2;
                }
            }
            continue;
        }

        // --- QK^T: each b-frag feeds 2 m-tiles ---
        float accS[2][8][4];
        #pragma unroll
        for (int mt = 0; mt < 2; mt++)
            #pragma unroll
            for (int ni = 0; ni < 8; ni++)
                #pragma unroll
                for (int r = 0; r < 4; r++) accS[mt][ni][r] = 0.f;
        #pragma unroll
        for (int kc = 0; kc < 8; kc++) {
            uint2 bp[8];
            #pragma unroll
            for (int ni = 0; ni < 8; ni++)
                bp[ni] = *reinterpret_cast<const uint2*>(
                    &Ks[(wc + ni*8 + g) * KP2 + kc*8 + 2*tg]);
            #pragma unroll
            for (int mt = 0; mt < 2; mt++)
                #pragma unroll
                for (int ni = 0; ni < 8; ni++)
                    mma_tf32(accS[mt][ni],
                             qf[kc][mt][0], qf[kc][mt][1], qf[kc][mt][2], qf[kc][mt][3],
                             bp[ni].x, bp[ni].y);
        }

        // --- E = exp2(s*0.125*log2e), mask, rowsum, store unnormalized ---
        #pragma unroll
        for (int mt = 0; mt < 2; mt++) {
            int rw = m0 + wr*32 + mt*16 + g;
            #pragma unroll
            for (int ni = 0; ni < 8; ni++) {
                int col = k0 + wc + ni*8 + 2*tg;
                float p0 = exp2f(accS[mt][ni][0]*SC2_);
                float p1 = exp2f(accS[mt][ni][1]*SC2_);
                float p2 = exp2f(accS[mt][ni][2]*SC2_);
                float p3 = exp2f(accS[mt][ni][3]*SC2_);
                if (diag) {
                    if (col     > rw    ) p0 = 0.f;
                    if (col + 1 > rw    ) p1 = 0.f;
                    if (col     > rw + 8) p2 = 0.f;
                    if (col + 1 > rw + 8) p3 = 0.f;
                }
                rs[mt][0] += p0 + p1;
                rs[mt][1] += p2 + p3;
                *reinterpret_cast<float2*>(Pp + (long long)rw       * TKV_ + col) = make_float2(p0, p1);
                *reinterpret_cast<float2*>(Pp + (long long)(rw + 8) * TKV_ + col) = make_float2(p2, p3);
                accS[mt][ni][0] = p0; accS[mt][ni][1] = p1;
                accS[mt][ni][2] = p2; accS[mt][ni][3] = p3;
            }
        }

        // --- AV: V b-frag (one LDS.64) feeds 2 m-tiles ---
        #pragma unroll
        for (int kc = 0; kc < 8; kc++) {
            uint32_t af[2][4];
            #pragma unroll
            for (int mt = 0; mt < 2; mt++) {
                af[mt][0] = f2tf32(accS[mt][kc][0]);
                af[mt][1] = f2tf32(accS[mt][kc][2]);
                af[mt][2] = f2tf32(accS[mt][kc][1]);
                af[mt][3] = f2tf32(accS[mt][kc][3]);
            }
            #pragma unroll
            for (int nj = 0; nj < 8; nj++) {
                uint2 bv = *reinterpret_cast<const uint2*>(
                    &Vs[(nj*8 + g) * VTP + wc + kc*8 + 2*tg]);
                #pragma unroll
                for (int mt = 0; mt < 2; mt++)
                    mma_tf32(accO[mt][nj], af[mt][0], af[mt][1], af[mt][2], af[mt][3],
                             bv.x, bv.y);
            }
        }
    }

    // ---- cross-group reduction (rowsum + partial O) ----
    #pragma unroll
    for (int mt = 0; mt < 2; mt++)
        #pragma unroll
        for (int p = 0; p < 2; p++) {
            float v = rs[mt][p];
            v += __shfl_xor_sync(0xffffffffu, v, 1);
            v += __shfl_xor_sync(0xffffffffu, v, 2);
            rs[mt][p] = v;
        }

    __syncthreads();
    float* redS = (float*)sm;              // [128] rowsums
    float* redO = (float*)sm + 256;        // [128][64] partial O
    if (grp == 1) {
        #pragma unroll
        for (int mt = 0; mt < 2; mt++) {
            int lr = wr*32 + mt*16 + g;
            if (tg == 0) {
                redS[lr]     = rs[mt][0];
                redS[lr + 8] = rs[mt][1];
            }
            #pragma unroll
            for (int nj = 0; nj < 8; nj++) {
                *reinterpret_cast<float2*>(&redO[(lr    ) * 64 + nj*8 + 2*tg]) =
                    make_float2(accO[mt][nj][0], accO[mt][nj][1]);
                *reinterpret_cast<float2*>(&redO[(lr + 8) * 64 + nj*8 + 2*tg]) =
                    make_float2(accO[mt][nj][2], accO[mt][nj][3]);
            }
        }
    }
    __syncthreads();

    if (grp == 0) {
        #pragma unroll
        for (int mt = 0; mt < 2; mt++) {
            int lr = wr*32 + mt*16 + g;
            float s0 = rs[mt][0] + redS[lr];
            float s1 = rs[mt][1] + redS[lr + 8];
            const float inv0 = 1.0f / s0;
            const float inv1 = 1.0f / s1;
            int rw = m0 + lr;
            if (tg == 0) {
                Invg[(long long)bh * TQ_ + rw]     = inv0;
                Invg[(long long)bh * TQ_ + rw + 8] = inv1;
            }
            #pragma unroll
            for (int nj = 0; nj < 8; nj++) {
                int col = nj*8 + 2*tg;
                float2 r0 = *reinterpret_cast<float2*>(&redO[(lr    ) * 64 + col]);
                float2 r1 = *reinterpret_cast<float2*>(&redO[(lr + 8) * 64 + col]);
                *reinterpret_cast<float2*>(Op + (long long)rw       * DM_ + col) =
                    make_float2((accO[mt][nj][0] + r0.x) * inv0,
                                (accO[mt][nj][1] + r0.y) * inv0);
                *reinterpret_cast<float2*>(Op + (long long)(rw + 8) * DM_ + col) =
                    make_float2((accO[mt][nj][2] + r1.x) * inv1,
                                (accO[mt][nj][3] + r1.y) * inv1);
            }
        }
    }
}

// ===================== normalize P (causal half only) =====================
__global__ void __launch_bounds__(128) normalize_P(
    float* __restrict__ P, const float* __restrict__ Inv)
{
    const long long r = blockIdx.x;
    const int q = (int)(r & (TQ_ - 1));
    const float s = Inv[r];
    float4* p = reinterpret_cast<float4*>(P + r * TKV_);
    const int n4 = (q + 4) >> 2;
    for (int i = threadIdx.x; i < n4; i += 128) {
        float4 v = p[i];
        v.x *= s; v.y *= s; v.z *= s; v.w *= s;
        p[i] = v;
    }
}

// ===================== launch =====================
extern "C" void kernel_launch(void* const* d_in, const int* in_sizes, int n_in,
                              void* d_out, int out_size)
{
    const float* q  = (const float*)d_in[0];
    const float* kv = (const float*)d_in[1];
    const float* Wq = (const float*)d_in[3];
    const float* bq = (const float*)d_in[4];
    const float* Wk = (const float*)d_in[5];
    const float* bk = (const float*)d_in[6];
    const float* Wv = (const float*)d_in[7];
    const float* bv = (const float*)d_in[8];
    const float* Wo = (const float*)d_in[9];
    const float* bo = (const float*)d_in[10];
    float* out = (float*)d_out;
    (void)in_sizes; (void)n_in;

    float *gQ, *gK, *gVT, *gS, *gATT, *gINV;
    cudaGetSymbolAddress((void**)&gQ,   g_Q);
    cudaGetSymbolAddress((void**)&gK,   g_K);
    cudaGetSymbolAddress((void**)&gVT,  g_VT);
    cudaGetSymbolAddress((void**)&gS,   g_S);
    cudaGetSymbolAddress((void**)&gATT, g_ATT);
    cudaGetSymbolAddress((void**)&gINV, g_INV);

    float* attn_dst = (out_size >= OUT_ELEMS + ATT_ELEMS) ? (out + OUT_ELEMS) : gS;

    static cudaStream_t s1 = nullptr, s2 = nullptr;
    static cudaEvent_t e0 = nullptr, e1 = nullptr, e2 = nullptr, e3 = nullptr, ez = nullptr;
    static bool init_done = false;
    if (!init_done) {
        cudaFuncSetAttribute(proj_gemm,
            cudaFuncAttributeMaxDynamicSharedMemorySize, PROJ_SMEM);
        cudaFuncSetAttribute(kv_pipe,
            cudaFuncAttributeMaxDynamicSharedMemorySize, KVP_SMEM);
        cudaFuncSetAttribute(fused_attn,
            cudaFuncAttributeMaxDynamicSharedMemorySize, FA_SMEM_BYTES);
        cudaStreamCreateWithFlags(&s1, cudaStreamNonBlocking);
        cudaStreamCreateWithFlags(&s2, cudaStreamNonBlocking);
        cudaEventCreateWithFlags(&e0, cudaEventDisableTiming);
        cudaEventCreateWithFlags(&e1, cudaEventDisableTiming);
        cudaEventCreateWithFlags(&e2, cudaEventDisableTiming);
        cudaEventCreateWithFlags(&e3, cudaEventDisableTiming);
        cudaEventCreateWithFlags(&ez, cudaEventDisableTiming);
        init_done = true;
    }

    // fork: kv proj on s1, zero-fill on s2, Q proj on main
    cudaEventRecord(e0, 0);
    cudaStreamWaitEvent(s1, e0, 0);
    cudaStreamWaitEvent(s2, e0, 0);
    kv_pipe<<<dim3(1, (B_*TKV_)/128, 2), 128, KVP_SMEM, s1>>>(
        kv, Wk, Wv, bk, bv, gK, gVT);
    cudaEventRecord(e1, s1);
    zero_P<<<dim3(TQ_/128, B_*NH_), 256, 0, s2>>>(attn_dst);
    cudaEventRecord(ez, s2);

    proj_gemm<<<dim3(DM_/128, (B_*TQ_)/128), 256, PROJ_SMEM>>>(q, Wq, gQ, bq, 2);

    // join kv, then fused attention on main
    cudaStreamWaitEvent(0, e1, 0);
    fused_attn<<<dim3(TQ_/128, B_*NH_), 256, FA_SMEM_BYTES>>>(
        gQ, gK, gVT, attn_dst, gATT, gINV);

    // fork: normalize on s1 overlaps final projection on main
    cudaEventRecord(e2, 0);
    cudaStreamWaitEvent(s1, e2, 0);
    normalize_P<<<B_*NH_*TQ_, 128, 0, s1>>>(attn_dst, gINV);
    cudaEventRecord(e3, s1);

    proj_gemm<<<dim3(DM_/128, (B_*TQ_)/128), 256, PROJ_SMEM>>>(gATT, Wo, out, bo, 0);
    cudaStreamWaitEvent(0, e3, 0);
    cudaStreamWaitEvent(0, ez, 0);
}

// round 14
// speedup vs baseline: 1.1108x; 1.0356x over previous
#include <cuda_runtime.h>
#include <cstdint>

#define B_   2
#define TQ_  2048
#define TKV_ 2048
#define DM_  1024
#define NH_  16
#define DH_  64
#define OUT_ELEMS (B_*TQ_*DM_)
#define ATT_ELEMS (B_*NH_*TQ_*TKV_)
#define SC2_ 0.18033688011112543f   /* 0.125 * log2(e) */

__device__ float g_Q[B_*TQ_*DM_];
__device__ float g_K[B_*TKV_*DH_];
__device__ float g_VT[B_*DH_*TKV_];
__device__ float g_S[ATT_ELEMS];
__device__ float g_ATT[B_*TQ_*DM_];
__device__ float g_INV[B_*NH_*TQ_];

__device__ __forceinline__ uint32_t f2tf32(float f) {
    uint32_t u;
    asm("cvt.rna.tf32.f32 %0, %1;" : "=r"(u) : "f"(f));
    return u;
}
__device__ __forceinline__ uint32_t cvt_u(uint32_t w) {
    return f2tf32(__uint_as_float(w));
}
__device__ __forceinline__ uint32_t smaddr(const void* p) {
    return (uint32_t)__cvta_generic_to_shared(p);
}
__device__ __forceinline__ void cp16(uint32_t dst, const void* src) {
    asm volatile("cp.async.cg.shared.global [%0], [%1], 16;" :: "r"(dst), "l"(src));
}
__device__ __forceinline__ void cp_commit() {
    asm volatile("cp.async.commit_group;");
}
template<int N> __device__ __forceinline__ void cp_wait() {
    asm volatile("cp.async.wait_group %0;" :: "n"(N));
}
__device__ __forceinline__ void barg128(int id) {
    asm volatile("bar.sync %0, %1;" :: "r"(id), "r"(128) : "memory");
}

__device__ __forceinline__ void mma_tf32(float c[4],
    uint32_t a0, uint32_t a1, uint32_t a2, uint32_t a3,
    uint32_t b0, uint32_t b1)
{
    asm volatile(
        "mma.sync.aligned.m16n8k8.row.col.f32.tf32.tf32.f32 "
        "{%0,%1,%2,%3},{%4,%5,%6,%7},{%8,%9},{%0,%1,%2,%3};"
        : "+f"(c[0]), "+f"(c[1]), "+f"(c[2]), "+f"(c[3])
        : "r"(a0), "r"(a1), "r"(a2), "r"(a3), "r"(b0), "r"(b1));
}

// ===================== pipelined TF32 GEMM core (3-stage cp.async) =====================
#define PK 36

template<int BN, int NTHR>
__device__ __forceinline__ void gemm_core(
    uint32_t* sm, const float* A, int lda, const float* Bp, int ldb,
    float* C, int ldc, const float* bias, int m0, int n0, int epi)
{
    const int STW = (128 + BN) * PK;
    const int tid = threadIdx.x;
    const int warpId = tid >> 5, lane = tid & 31;
    const int warpM = warpId & 1, warpN = warpId >> 1;
    const int g = lane >> 2, tg = lane & 3;

    constexpr int ACH = 1024 / NTHR;
    constexpr int BCH = (BN * 8) / NTHR;

    auto issue = [&](int t, int s) {
        const float* Asrc = A + (long long)m0 * lda + t * 32;
        uint32_t abase = smaddr(sm + s * STW);
        #pragma unroll
        for (int i = 0; i < ACH; i++) {
            int f = tid + i * NTHR;
            int row = f >> 3, c = f & 7;
            cp16(abase + (row * PK + c * 4) * 4, Asrc + (long long)row * lda + c * 4);
        }
        const float* Bsrc = Bp + (long long)n0 * ldb + t * 32;
        uint32_t bbase = smaddr(sm + s * STW + 128 * PK);
        #pragma unroll
        for (int i = 0; i < BCH; i++) {
            int f = tid + i * NTHR;
            int row = f >> 3, c = f & 7;
            cp16(bbase + (row * PK + c * 4) * 4, Bsrc + (long long)row * ldb + c * 4);
        }
        cp_commit();
    };

    float acc[4][4][4];
    #pragma unroll
    for (int mi = 0; mi < 4; mi++)
        #pragma unroll
        for (int ni = 0; ni < 4; ni++)
            #pragma unroll
            for (int r = 0; r < 4; r++) acc[mi][ni][r] = 0.f;

    const int T = 1024 / 32;
    issue(0, 0);
    issue(1, 1);

    for (int t = 0; t < T; t++) {
        if (t < T - 1) cp_wait<1>(); else cp_wait<0>();
        __syncthreads();
        if (t + 2 < T) issue(t + 2, (t + 2) % 3);

        const uint32_t* As = sm + (t % 3) * STW;
        const uint32_t* Bs = As + 128 * PK;

        #pragma unroll
        for (int kk = 0; kk < 32; kk += 8) {
            uint32_t a[4][4], b[4][2];
            #pragma unroll
            for (int mi = 0; mi < 4; mi++) {
                int mB = warpM * 64 + mi * 16;
                a[mi][0] = cvt_u(As[(mB + g    ) * PK + kk + tg    ]);
                a[mi][1] = cvt_u(As[(mB + g + 8) * PK + kk + tg    ]);
                a[mi][2] = cvt_u(As[(mB + g    ) * PK + kk + tg + 4]);
                a[mi][3] = cvt_u(As[(mB + g + 8) * PK + kk + tg + 4]);
            }
            #pragma unroll
            for (int ni = 0; ni < 4; ni++) {
                int nB = warpN * 32 + ni * 8;
                b[ni][0] = cvt_u(Bs[(nB + g) * PK + kk + tg    ]);
                b[ni][1] = cvt_u(Bs[(nB + g) * PK + kk + tg + 4]);
            }
            #pragma unroll
            for (int mi = 0; mi < 4; mi++)
                #pragma unroll
                for (int ni = 0; ni < 4; ni++)
                    mma_tf32(acc[mi][ni], a[mi][0], a[mi][1], a[mi][2], a[mi][3],
                             b[ni][0], b[ni][1]);
        }
    }

    #pragma unroll
    for (int mi = 0; mi < 4; mi++) {
        #pragma unroll
        for (int ni = 0; ni < 4; ni++) {
            int m = m0 + warpM * 64 + mi * 16 + g;
            int n = n0 + warpN * 32 + ni * 8 + 2 * tg;
            float b0 = bias[n], b1 = bias[n + 1];
            float v00 = acc[mi][ni][0] + b0, v01 = acc[mi][ni][1] + b1;
            float v10 = acc[mi][ni][2] + b0, v11 = acc[mi][ni][3] + b1;
            if (epi == 0) {
                *reinterpret_cast<float2*>(C + (long long)m * ldc + n)       = make_float2(v00, v01);
                *reinterpret_cast<float2*>(C + (long long)(m + 8) * ldc + n) = make_float2(v10, v11);
            } else {
                float r00 = __uint_as_float(f2tf32(v00));
                float r01 = __uint_as_float(f2tf32(v01));
                float r10 = __uint_as_float(f2tf32(v10));
                float r11 = __uint_as_float(f2tf32(v11));
                if (epi == 1) {
                    int base = n & ~7;
                    int j0 = n & 7, j1 = j0 + 1;
                    int n0p = base + ((j0 < 4) ? 2*j0 : 2*j0 - 7);
                    int n1p = base + ((j1 < 4) ? 2*j1 : 2*j1 - 7);
                    C[(long long)m * ldc + n0p] = r00;
                    C[(long long)m * ldc + n1p] = r01;
                    C[(long long)(m + 8) * ldc + n0p] = r10;
                    C[(long long)(m + 8) * ldc + n1p] = r11;
                } else if (epi == 3) {
                    long long bb  = (long long)(m >> 11) * DH_ * TKV_;
                    int kv0 = m & (TKV_ - 1);
                    C[bb + (long long)n       * TKV_ + kv0    ] = r00;
                    C[bb + (long long)(n + 1) * TKV_ + kv0    ] = r01;
                    C[bb + (long long)n       * TKV_ + kv0 + 8] = r10;
                    C[bb + (long long)(n + 1) * TKV_ + kv0 + 8] = r11;
                } else {
                    *reinterpret_cast<float2*>(C + (long long)m * ldc + n)       = make_float2(r00, r01);
                    *reinterpret_cast<float2*>(C + (long long)(m + 8) * ldc + n) = make_float2(r10, r11);
                }
            }
        }
    }
}

#define PROJ_SMEM ((3*(128+128)*PK)*4)
#define KVP_SMEM  ((3*(128+64)*PK)*4)

__global__ void __launch_bounds__(256, 2) proj_gemm(
    const float* __restrict__ A, const float* __restrict__ Bp,
    float* __restrict__ C, const float* __restrict__ bias, int epi)
{
    extern __shared__ uint32_t sm[];
    gemm_core<128, 256>(sm, A, DM_, Bp, DM_, C, DM_, bias,
                        blockIdx.y * 128, blockIdx.x * 128, epi);
}

__global__ void __launch_bounds__(128) kv_pipe(
    const float* __restrict__ A,
    const float* __restrict__ Wk_, const float* __restrict__ Wv_,
    const float* __restrict__ bk_, const float* __restrict__ bv_,
    float* __restrict__ CK, float* __restrict__ CVT)
{
    extern __shared__ uint32_t sm[];
    const float* Bp   = blockIdx.z ? Wv_ : Wk_;
    const float* bias = blockIdx.z ? bv_ : bk_;
    float* C          = blockIdx.z ? CVT : CK;
    gemm_core<64, 128>(sm, A, DM_, Bp, DM_, C, DH_, bias,
                       blockIdx.y * 128, 0, blockIdx.z ? 3 : 1);
}

// ===================== zero upper-triangle of P =====================
__global__ void __launch_bounds__(256) zero_P(float* __restrict__ P)
{
    const int m0 = blockIdx.x * 128;
    float* Pp = P + (long long)blockIdx.y * TQ_ * TKV_;
    const int zc0 = m0 + 128;
    const int W = (TKV_ - zc0) >> 2;
    if (W <= 0) return;
    float4 z = make_float4(0.f, 0.f, 0.f, 0.f);
    for (int idx = threadIdx.x; idx < 128 * W; idx += 256) {
        int r = idx / W, c4 = idx - r * W;
        *reinterpret_cast<float4*>(Pp + (long long)(m0 + r) * TKV_ + zc0 + c4*4) = z;
    }
}

// ===================== Fused attention: paired q-blocks, uniform 17-tile CTAs =====================
#define KP2 72
#define VTP 136
#define KBW (128*KP2)
#define VTW (64*VTP)
#define FA_SMEM_BYTES ((3*KBW + 3*VTW)*4)   // 215040 B
#define NQB (TQ_/128)

__global__ void __launch_bounds__(256, 1) fused_attn(
    const float* __restrict__ Qg, const float* __restrict__ Kg,
    const float* __restrict__ VTg, float* __restrict__ Pg,
    float* __restrict__ Og, float* __restrict__ Invg)
{
    extern __shared__ uint32_t sm[];

    const int px = blockIdx.x;        // 0..NQB/2-1
    const int bh = blockIdx.y;
    const int b  = bh >> 4, h = bh & 15;

    const float* Qp  = Qg  + (long long)b * TQ_ * DM_ + h * DH_;
    const float* Kp  = Kg  + (long long)b * TKV_ * DH_;
    const float* VTp = VTg + (long long)b * DH_ * TKV_;
    float* Pp = Pg + (long long)bh * TQ_ * TKV_;
    float* Op = Og + (long long)b * TQ_ * DM_ + h * DH_;

    const int tid = threadIdx.x;
    const int wid = tid >> 5;
    const int wr  = wid & 3;          // 32-row band
    const int grp = wid >> 2;         // kv half
    const int wc  = grp * 64;
    const int ltid = tid & 127;
    const int lane = tid & 31;
    const int g = lane >> 2, tg = lane & 3;

    auto issueHalf = [&](int t, int s) {
        uint32_t kb = smaddr(sm + s * KBW);
        uint32_t vb = smaddr(sm + 3 * KBW + s * VTW);
        #pragma unroll
        for (int i = 0; i < 8; i++) {
            int f = ltid + i * 128;
            int row = wc + (f >> 4), c = f & 15;
            cp16(kb + (row * KP2 + c * 4) * 4,
                 Kp + (long long)(t * 128 + row) * DH_ + c * 4);
        }
        #pragma unroll
        for (int i = 0; i < 8; i++) {
            int f = ltid + i * 128;
            int nrow = f >> 4;
            int ccol = wc + (f & 15) * 4;
            cp16(vb + (nrow * VTP + ccol) * 4,
                 VTp + (long long)nrow * TKV_ + t * 128 + ccol);
        }
        cp_commit();
    };

    // Two phases: heavy q-block first (qb = NQB-1-px), then light (qb = px).
    #pragma unroll 1
    for (int ph = 0; ph < 2; ph++) {
        const int qb = ph ? px : (NQB - 1 - px);
        const int m0 = qb * 128;
        const int nT = qb + 1;

        __syncthreads();   // protect smem reuse across phases

        // ---- stage Q (pre-rounded tf32) ----
        {
            uint32_t qbse = smaddr(sm);
            #pragma unroll
            for (int i = 0; i < 8; i++) {
                int f = tid + i * 256;
                int row = f >> 4, c = f & 15;
                cp16(qbse + (row * KP2 + c * 4) * 4,
                     Qp + (long long)(m0 + row) * DM_ + c * 4);
            }
            cp_commit();
            cp_wait<0>();
        }
        __syncthreads();
        uint32_t qf[8][2][4];
        #pragma unroll
        for (int kc = 0; kc < 8; kc++)
            #pragma unroll
            for (int mt = 0; mt < 2; mt++) {
                int rw = wr*32 + mt*16 + g;
                qf[kc][mt][0] = sm[(rw    ) * KP2 + kc*8 + tg    ];
                qf[kc][mt][1] = sm[(rw + 8) * KP2 + kc*8 + tg    ];
                qf[kc][mt][2] = sm[(rw    ) * KP2 + kc*8 + tg + 4];
                qf[kc][mt][3] = sm[(rw + 8) * KP2 + kc*8 + tg + 4];
            }
        __syncthreads();

        float rs[2][2];
        rs[0][0] = rs[0][1] = rs[1][0] = rs[1][1] = 0.f;
        float accO[2][8][4];
        #pragma unroll
        for (int mt = 0; mt < 2; mt++)
            #pragma unroll
            for (int nj = 0; nj < 8; nj++)
                #pragma unroll
                for (int r = 0; r < 4; r++) accO[mt][nj][r] = 0.f;

        issueHalf(0, 0);
        if (nT > 1) issueHalf(1, 1);

        for (int t = 0; t < nT; t++) {
            if (t < nT - 1) cp_wait<1>(); else cp_wait<0>();
            barg128(1 + grp);
            if (t + 2 < nT) issueHalf(t + 2, (t + 2) % 3);

            const int k0 = t * 128;
            const uint32_t* Ks = sm + (t % 3) * KBW;
            const uint32_t* Vs = sm + 3 * KBW + (t % 3) * VTW;
            const bool diag = (t == nT - 1);

            if (diag && wc >= wr * 32 + 32) {
                float2 z2 = make_float2(0.f, 0.f);
                #pragma unroll
                for (int mt = 0; mt < 2; mt++) {
                    int rw = m0 + wr*32 + mt*16 + g;
                    #pragma unroll
                    for (int ni = 0; ni < 8; ni++) {
                        int col = k0 + wc + ni*8 + 2*tg;
                        *reinterpret_cast<float2*>(Pp + (long long)rw       * TKV_ + col) = z2;
                        *reinterpret_cast<float2*>(Pp + (long long)(rw + 8) * TKV_ + col) = z2;
                    }
                }
                continue;
            }

            // --- QK^T ---
            float accS[2][8][4];
            #pragma unroll
            for (int mt = 0; mt < 2; mt++)
                #pragma unroll
                for (int ni = 0; ni < 8; ni++)
                    #pragma unroll
                    for (int r = 0; r < 4; r++) accS[mt][ni][r] = 0.f;
            #pragma unroll
            for (int kc = 0; kc < 8; kc++) {
                uint2 bp[8];
                #pragma unroll
                for (int ni = 0; ni < 8; ni++)
                    bp[ni] = *reinterpret_cast<const uint2*>(
                        &Ks[(wc + ni*8 + g) * KP2 + kc*8 + 2*tg]);
                #pragma unroll
                for (int mt = 0; mt < 2; mt++)
                    #pragma unroll
                    for (int ni = 0; ni < 8; ni++)
                        mma_tf32(accS[mt][ni],
                                 qf[kc][mt][0], qf[kc][mt][1], qf[kc][mt][2], qf[kc][mt][3],
                                 bp[ni].x, bp[ni].y);
            }

            // --- E = exp2(s*SC2), mask, rowsum, store ---
            #pragma unroll
            for (int mt = 0; mt < 2; mt++) {
                int rw = m0 + wr*32 + mt*16 + g;
                #pragma unroll
                for (int ni = 0; ni < 8; ni++) {
                    int col = k0 + wc + ni*8 + 2*tg;
                    float p0 = exp2f(accS[mt][ni][0]*SC2_);
                    float p1 = exp2f(accS[mt][ni][1]*SC2_);
                    float p2 = exp2f(accS[mt][ni][2]*SC2_);
                    float p3 = exp2f(accS[mt][ni][3]*SC2_);
                    if (diag) {
                        if (col     > rw    ) p0 = 0.f;
                        if (col + 1 > rw    ) p1 = 0.f;
                        if (col     > rw + 8) p2 = 0.f;
                        if (col + 1 > rw + 8) p3 = 0.f;
                    }
                    rs[mt][0] += p0 + p1;
                    rs[mt][1] += p2 + p3;
                    *reinterpret_cast<float2*>(Pp + (long long)rw       * TKV_ + col) = make_float2(p0, p1);
                    *reinterpret_cast<float2*>(Pp + (long long)(rw + 8) * TKV_ + col) = make_float2(p2, p3);
                    accS[mt][ni][0] = p0; accS[mt][ni][1] = p1;
                    accS[mt][ni][2] = p2; accS[mt][ni][3] = p3;
                }
            }

            // --- AV ---
            #pragma unroll
            for (int kc = 0; kc < 8; kc++) {
                uint32_t af[2][4];
                #pragma unroll
                for (int mt = 0; mt < 2; mt++) {
                    af[mt][0] = f2tf32(accS[mt][kc][0]);
                    af[mt][1] = f2tf32(accS[mt][kc][2]);
                    af[mt][2] = f2tf32(accS[mt][kc][1]);
                    af[mt][3] = f2tf32(accS[mt][kc][3]);
                }
                #pragma unroll
                for (int nj = 0; nj < 8; nj++) {
                    uint2 bv = *reinterpret_cast<const uint2*>(
                        &Vs[(nj*8 + g) * VTP + wc + kc*8 + 2*tg]);
                    #pragma unroll
                    for (int mt = 0; mt < 2; mt++)
                        mma_tf32(accO[mt][nj], af[mt][0], af[mt][1], af[mt][2], af[mt][3],
                                 bv.x, bv.y);
                }
            }
        }

        // ---- cross-group reduction ----
        #pragma unroll
        for (int mt = 0; mt < 2; mt++)
            #pragma unroll
            for (int p = 0; p < 2; p++) {
                float v = rs[mt][p];
                v += __shfl_xor_sync(0xffffffffu, v, 1);
                v += __shfl_xor_sync(0xffffffffu, v, 2);
                rs[mt][p] = v;
            }

        __syncthreads();
        float* redS = (float*)sm;
        float* redO = (float*)sm + 256;
        if (grp == 1) {
            #pragma unroll
            for (int mt = 0; mt < 2; mt++) {
                int lr = wr*32 + mt*16 + g;
                if (tg == 0) {
                    redS[lr]     = rs[mt][0];
                    redS[lr + 8] = rs[mt][1];
                }
                #pragma unroll
                for (int nj = 0; nj < 8; nj++) {
                    *reinterpret_cast<float2*>(&redO[(lr    ) * 64 + nj*8 + 2*tg]) =
                        make_float2(accO[mt][nj][0], accO[mt][nj][1]);
                    *reinterpret_cast<float2*>(&redO[(lr + 8) * 64 + nj*8 + 2*tg]) =
                        make_float2(accO[mt][nj][2], accO[mt][nj][3]);
                }
            }
        }
        __syncthreads();

        if (grp == 0) {
            #pragma unroll
            for (int mt = 0; mt < 2; mt++) {
                int lr = wr*32 + mt*16 + g;
                float s0 = rs[mt][0] + redS[lr];
                float s1 = rs[mt][1] + redS[lr + 8];
                const float inv0 = 1.0f / s0;
                const float inv1 = 1.0f / s1;
                int rw = m0 + lr;
                if (tg == 0) {
                    Invg[(long long)bh * TQ_ + rw]     = inv0;
                    Invg[(long long)bh * TQ_ + rw + 8] = inv1;
                }
                #pragma unroll
                for (int nj = 0; nj < 8; nj++) {
                    int col = nj*8 + 2*tg;
                    float2 r0 = *reinterpret_cast<float2*>(&redO[(lr    ) * 64 + col]);
                    float2 r1 = *reinterpret_cast<float2*>(&redO[(lr + 8) * 64 + col]);
                    *reinterpret_cast<float2*>(Op + (long long)rw       * DM_ + col) =
                        make_float2((accO[mt][nj][0] + r0.x) * inv0,
                                    (accO[mt][nj][1] + r0.y) * inv0);
                    *reinterpret_cast<float2*>(Op + (long long)(rw + 8) * DM_ + col) =
                        make_float2((accO[mt][nj][2] + r1.x) * inv1,
                                    (accO[mt][nj][3] + r1.y) * inv1);
                }
            }
        }
    }
}

// ===================== normalize P (causal half only) =====================
__global__ void __launch_bounds__(128) normalize_P(
    float* __restrict__ P, const float* __restrict__ Inv)
{
    const long long r = blockIdx.x;
    const int q = (int)(r & (TQ_ - 1));
    const float s = Inv[r];
    float4* p = reinterpret_cast<float4*>(P + r * TKV_);
    const int n4 = (q + 4) >> 2;
    for (int i = threadIdx.x; i < n4; i += 128) {
        float4 v = p[i];
        v.x *= s; v.y *= s; v.z *= s; v.w *= s;
        p[i] = v;
    }
}

// ===================== launch =====================
extern "C" void kernel_launch(void* const* d_in, const int* in_sizes, int n_in,
                              void* d_out, int out_size)
{
    const float* q  = (const float*)d_in[0];
    const float* kv = (const float*)d_in[1];
    const float* Wq = (const float*)d_in[3];
    const float* bq = (const float*)d_in[4];
    const float* Wk = (const float*)d_in[5];
    const float* bk = (const float*)d_in[6];
    const float* Wv = (const float*)d_in[7];
    const float* bv = (const float*)d_in[8];
    const float* Wo = (const float*)d_in[9];
    const float* bo = (const float*)d_in[10];
    float* out = (float*)d_out;
    (void)in_sizes; (void)n_in;

    float *gQ, *gK, *gVT, *gS, *gATT, *gINV;
    cudaGetSymbolAddress((void**)&gQ,   g_Q);
    cudaGetSymbolAddress((void**)&gK,   g_K);
    cudaGetSymbolAddress((void**)&gVT,  g_VT);
    cudaGetSymbolAddress((void**)&gS,   g_S);
    cudaGetSymbolAddress((void**)&gATT, g_ATT);
    cudaGetSymbolAddress((void**)&gINV, g_INV);

    float* attn_dst = (out_size >= OUT_ELEMS + ATT_ELEMS) ? (out + OUT_ELEMS) : gS;

    static cudaStream_t s1 = nullptr, s2 = nullptr;
    static cudaEvent_t e0 = nullptr, e1 = nullptr, e2 = nullptr, e3 = nullptr, ez = nullptr;
    static bool init_done = false;
    if (!init_done) {
        cudaFuncSetAttribute(proj_gemm,
            cudaFuncAttributeMaxDynamicSharedMemorySize, PROJ_SMEM);
        cudaFuncSetAttribute(kv_pipe,
            cudaFuncAttributeMaxDynamicSharedMemorySize, KVP_SMEM);
        cudaFuncSetAttribute(fused_attn,
            cudaFuncAttributeMaxDynamicSharedMemorySize, FA_SMEM_BYTES);
        cudaStreamCreateWithFlags(&s1, cudaStreamNonBlocking);
        cudaStreamCreateWithFlags(&s2, cudaStreamNonBlocking);
        cudaEventCreateWithFlags(&e0, cudaEventDisableTiming);
        cudaEventCreateWithFlags(&e1, cudaEventDisableTiming);
        cudaEventCreateWithFlags(&e2, cudaEventDisableTiming);
        cudaEventCreateWithFlags(&e3, cudaEventDisableTiming);
        cudaEventCreateWithFlags(&ez, cudaEventDisableTiming);
        init_done = true;
    }

    // fork: kv proj on s1, zero-fill on s2, Q proj on main
    cudaEventRecord(e0, 0);
    cudaStreamWaitEvent(s1, e0, 0);
    cudaStreamWaitEvent(s2, e0, 0);
    kv_pipe<<<dim3(1, (B_*TKV_)/128, 2), 128, KVP_SMEM, s1>>>(
        kv, Wk, Wv, bk, bv, gK, gVT);
    cudaEventRecord(e1, s1);
    zero_P<<<dim3(TQ_/128, B_*NH_), 256, 0, s2>>>(attn_dst);
    cudaEventRecord(ez, s2);

    proj_gemm<<<dim3(DM_/128, (B_*TQ_)/128), 256, PROJ_SMEM>>>(q, Wq, gQ, bq, 2);

    // join kv, then fused attention on main (paired q-blocks: uniform CTAs)
    cudaStreamWaitEvent(0, e1, 0);
    fused_attn<<<dim3(NQB/2, B_*NH_), 256, FA_SMEM_BYTES>>>(
        gQ, gK, gVT, attn_dst, gATT, gINV);

    // fork: normalize on s1 overlaps final projection on main
    cudaEventRecord(e2, 0);
    cudaStreamWaitEvent(s1, e2, 0);
    normalize_P<<<B_*NH_*TQ_, 128, 0, s1>>>(attn_dst, gINV);
    cudaEventRecord(e3, s1);

    proj_gemm<<<dim3(DM_/128, (B_*TQ_)/128), 256, PROJ_SMEM>>>(gATT, Wo, out, bo, 0);
    cudaStreamWaitEvent(0, e3, 0);
    cudaStreamWaitEvent(0, ez, 0);
}

// round 15
// speedup vs baseline: 1.1222x; 1.0102x over previous
#include <cuda_runtime.h>
#include <cstdint>

#define B_   2
#define TQ_  2048
#define TKV_ 2048
#define DM_  1024
#define NH_  16
#define DH_  64
#define OUT_ELEMS (B_*TQ_*DM_)
#define ATT_ELEMS (B_*NH_*TQ_*TKV_)
#define SC2_ 0.18033688011112543f   /* 0.125 * log2(e) */

__device__ float g_Q[B_*TQ_*DM_];
__device__ float g_K[B_*TKV_*DH_];
__device__ float g_VT[B_*DH_*TKV_];
__device__ float g_S[ATT_ELEMS];
__device__ float g_ATT[B_*TQ_*DM_];
__device__ float g_INV[B_*NH_*TQ_];
__device__ int   g_WQ;               // persistent work counter

__device__ __forceinline__ uint32_t f2tf32(float f) {
    uint32_t u;
    asm("cvt.rna.tf32.f32 %0, %1;" : "=r"(u) : "f"(f));
    return u;
}
__device__ __forceinline__ uint32_t cvt_u(uint32_t w) {
    return f2tf32(__uint_as_float(w));
}
__device__ __forceinline__ uint32_t smaddr(const void* p) {
    return (uint32_t)__cvta_generic_to_shared(p);
}
__device__ __forceinline__ void cp16(uint32_t dst, const void* src) {
    asm volatile("cp.async.cg.shared.global [%0], [%1], 16;" :: "r"(dst), "l"(src));
}
__device__ __forceinline__ void cp_commit() {
    asm volatile("cp.async.commit_group;");
}
template<int N> __device__ __forceinline__ void cp_wait() {
    asm volatile("cp.async.wait_group %0;" :: "n"(N));
}
__device__ __forceinline__ void barg128(int id) {
    asm volatile("bar.sync %0, %1;" :: "r"(id), "r"(128) : "memory");
}

__device__ __forceinline__ void mma_tf32(float c[4],
    uint32_t a0, uint32_t a1, uint32_t a2, uint32_t a3,
    uint32_t b0, uint32_t b1)
{
    asm volatile(
        "mma.sync.aligned.m16n8k8.row.col.f32.tf32.tf32.f32 "
        "{%0,%1,%2,%3},{%4,%5,%6,%7},{%8,%9},{%0,%1,%2,%3};"
        : "+f"(c[0]), "+f"(c[1]), "+f"(c[2]), "+f"(c[3])
        : "r"(a0), "r"(a1), "r"(a2), "r"(a3), "r"(b0), "r"(b1));
}

// ===================== pipelined TF32 GEMM core (3-stage cp.async) =====================
#define PK 36

template<int BN, int NTHR>
__device__ __forceinline__ void gemm_core(
    uint32_t* sm, const float* A, int lda, const float* Bp, int ldb,
    float* C, int ldc, const float* bias, int m0, int n0, int epi)
{
    const int STW = (128 + BN) * PK;
    const int tid = threadIdx.x;
    const int warpId = tid >> 5, lane = tid & 31;
    const int warpM = warpId & 1, warpN = warpId >> 1;
    const int g = lane >> 2, tg = lane & 3;

    constexpr int ACH = 1024 / NTHR;
    constexpr int BCH = (BN * 8) / NTHR;

    auto issue = [&](int t, int s) {
        const float* Asrc = A + (long long)m0 * lda + t * 32;
        uint32_t abase = smaddr(sm + s * STW);
        #pragma unroll
        for (int i = 0; i < ACH; i++) {
            int f = tid + i * NTHR;
            int row = f >> 3, c = f & 7;
            cp16(abase + (row * PK + c * 4) * 4, Asrc + (long long)row * lda + c * 4);
        }
        const float* Bsrc = Bp + (long long)n0 * ldb + t * 32;
        uint32_t bbase = smaddr(sm + s * STW + 128 * PK);
        #pragma unroll
        for (int i = 0; i < BCH; i++) {
            int f = tid + i * NTHR;
            int row = f >> 3, c = f & 7;
            cp16(bbase + (row * PK + c * 4) * 4, Bsrc + (long long)row * ldb + c * 4);
        }
        cp_commit();
    };

    float acc[4][4][4];
    #pragma unroll
    for (int mi = 0; mi < 4; mi++)
        #pragma unroll
        for (int ni = 0; ni < 4; ni++)
            #pragma unroll
            for (int r = 0; r < 4; r++) acc[mi][ni][r] = 0.f;

    const int T = 1024 / 32;
    issue(0, 0);
    issue(1, 1);

    for (int t = 0; t < T; t++) {
        if (t < T - 1) cp_wait<1>(); else cp_wait<0>();
        __syncthreads();
        if (t + 2 < T) issue(t + 2, (t + 2) % 3);

        const uint32_t* As = sm + (t % 3) * STW;
        const uint32_t* Bs = As + 128 * PK;

        #pragma unroll
        for (int kk = 0; kk < 32; kk += 8) {
            uint32_t a[4][4], b[4][2];
            #pragma unroll
            for (int mi = 0; mi < 4; mi++) {
                int mB = warpM * 64 + mi * 16;
                a[mi][0] = cvt_u(As[(mB + g    ) * PK + kk + tg    ]);
                a[mi][1] = cvt_u(As[(mB + g + 8) * PK + kk + tg    ]);
                a[mi][2] = cvt_u(As[(mB + g    ) * PK + kk + tg + 4]);
                a[mi][3] = cvt_u(As[(mB + g + 8) * PK + kk + tg + 4]);
            }
            #pragma unroll
            for (int ni = 0; ni < 4; ni++) {
                int nB = warpN * 32 + ni * 8;
                b[ni][0] = cvt_u(Bs[(nB + g) * PK + kk + tg    ]);
                b[ni][1] = cvt_u(Bs[(nB + g) * PK + kk + tg + 4]);
            }
            #pragma unroll
            for (int mi = 0; mi < 4; mi++)
                #pragma unroll
                for (int ni = 0; ni < 4; ni++)
                    mma_tf32(acc[mi][ni], a[mi][0], a[mi][1], a[mi][2], a[mi][3],
                             b[ni][0], b[ni][1]);
        }
    }

    #pragma unroll
    for (int mi = 0; mi < 4; mi++) {
        #pragma unroll
        for (int ni = 0; ni < 4; ni++) {
            int m = m0 + warpM * 64 + mi * 16 + g;
            int n = n0 + warpN * 32 + ni * 8 + 2 * tg;
            float b0 = bias[n], b1 = bias[n + 1];
            float v00 = acc[mi][ni][0] + b0, v01 = acc[mi][ni][1] + b1;
            float v10 = acc[mi][ni][2] + b0, v11 = acc[mi][ni][3] + b1;
            if (epi == 0) {
                *reinterpret_cast<float2*>(C + (long long)m * ldc + n)       = make_float2(v00, v01);
                *reinterpret_cast<float2*>(C + (long long)(m + 8) * ldc + n) = make_float2(v10, v11);
            } else {
                float r00 = __uint_as_float(f2tf32(v00));
                float r01 = __uint_as_float(f2tf32(v01));
                float r10 = __uint_as_float(f2tf32(v10));
                float r11 = __uint_as_float(f2tf32(v11));
                if (epi == 1) {
                    int base = n & ~7;
                    int j0 = n & 7, j1 = j0 + 1;
                    int n0p = base + ((j0 < 4) ? 2*j0 : 2*j0 - 7);
                    int n1p = base + ((j1 < 4) ? 2*j1 : 2*j1 - 7);
                    C[(long long)m * ldc + n0p] = r00;
                    C[(long long)m * ldc + n1p] = r01;
                    C[(long long)(m + 8) * ldc + n0p] = r10;
                    C[(long long)(m + 8) * ldc + n1p] = r11;
                } else if (epi == 3) {
                    long long bb  = (long long)(m >> 11) * DH_ * TKV_;
                    int kv0 = m & (TKV_ - 1);
                    C[bb + (long long)n       * TKV_ + kv0    ] = r00;
                    C[bb + (long long)(n + 1) * TKV_ + kv0    ] = r01;
                    C[bb + (long long)n       * TKV_ + kv0 + 8] = r10;
                    C[bb + (long long)(n + 1) * TKV_ + kv0 + 8] = r11;
                } else {
                    *reinterpret_cast<float2*>(C + (long long)m * ldc + n)       = make_float2(r00, r01);
                    *reinterpret_cast<float2*>(C + (long long)(m + 8) * ldc + n) = make_float2(r10, r11);
                }
            }
        }
    }
}

#define PROJ_SMEM ((3*(128+128)*PK)*4)
#define KVP_SMEM  ((3*(128+64)*PK)*4)

__global__ void __launch_bounds__(256, 2) proj_gemm(
    const float* __restrict__ A, const float* __restrict__ Bp,
    float* __restrict__ C, const float* __restrict__ bias, int epi)
{
    extern __shared__ uint32_t sm[];
    gemm_core<128, 256>(sm, A, DM_, Bp, DM_, C, DM_, bias,
                        blockIdx.y * 128, blockIdx.x * 128, epi);
}

__global__ void __launch_bounds__(128) kv_pipe(
    const float* __restrict__ A,
    const float* __restrict__ Wk_, const float* __restrict__ Wv_,
    const float* __restrict__ bk_, const float* __restrict__ bv_,
    float* __restrict__ CK, float* __restrict__ CVT)
{
    extern __shared__ uint32_t sm[];
    const float* Bp   = blockIdx.z ? Wv_ : Wk_;
    const float* bias = blockIdx.z ? bv_ : bk_;
    float* C          = blockIdx.z ? CVT : CK;
    gemm_core<64, 128>(sm, A, DM_, Bp, DM_, C, DH_, bias,
                       blockIdx.y * 128, 0, blockIdx.z ? 3 : 1);
}

// ===================== zero upper-triangle of P =====================
__global__ void __launch_bounds__(256) zero_P(float* __restrict__ P)
{
    const int m0 = blockIdx.x * 128;
    float* Pp = P + (long long)blockIdx.y * TQ_ * TKV_;
    const int zc0 = m0 + 128;
    const int W = (TKV_ - zc0) >> 2;
    if (W <= 0) return;
    float4 z = make_float4(0.f, 0.f, 0.f, 0.f);
    for (int idx = threadIdx.x; idx < 128 * W; idx += 256) {
        int r = idx / W, c4 = idx - r * W;
        *reinterpret_cast<float4*>(Pp + (long long)(m0 + r) * TKV_ + zc0 + c4*4) = z;
    }
}

__global__ void reset_ctr() { g_WQ = 0; }

// ===================== Fused attention: persistent work-stealing CTAs =====================
#define KP2 72
#define VTP 136
#define KBW (128*KP2)
#define VTW (64*VTP)
#define FA_SMEM_BYTES ((3*KBW + 3*VTW)*4)   // 215040 B
#define NQB (TQ_/128)
#define NWORK (NQB * B_ * NH_)               // 512 work units

__global__ void __launch_bounds__(256, 1) fused_attn(
    const float* __restrict__ Qg, const float* __restrict__ Kg,
    const float* __restrict__ VTg, float* __restrict__ Pg,
    float* __restrict__ Og, float* __restrict__ Invg)
{
    extern __shared__ uint32_t sm[];
    __shared__ int s_w;

    const int tid = threadIdx.x;
    const int wid = tid >> 5;
    const int wr  = wid & 3;          // 32-row band
    const int grp = wid >> 2;         // kv half
    const int wc  = grp * 64;
    const int ltid = tid & 127;
    const int lane = tid & 31;
    const int g = lane >> 2, tg = lane & 3;

    for (;;) {
        __syncthreads();              // smem reuse guard + s_w stability
        if (tid == 0) s_w = atomicAdd(&g_WQ, 1);
        __syncthreads();
        const int w = s_w;
        if (w >= NWORK) break;

        // heavy-first: qb descends as w grows
        const int qb = NQB - 1 - (w >> 5);
        const int bh = w & 31;
        const int b  = bh >> 4, h = bh & 15;
        const int m0 = qb * 128;
        const int nT = qb + 1;

        const float* Qp  = Qg  + (long long)b * TQ_ * DM_ + h * DH_;
        const float* Kp  = Kg  + (long long)b * TKV_ * DH_;
        const float* VTp = VTg + (long long)b * DH_ * TKV_;
        float* Pp = Pg + (long long)bh * TQ_ * TKV_;
        float* Op = Og + (long long)b * TQ_ * DM_ + h * DH_;

        auto issueHalf = [&](int t, int s) {
            uint32_t kb = smaddr(sm + s * KBW);
            uint32_t vb = smaddr(sm + 3 * KBW + s * VTW);
            #pragma unroll
            for (int i = 0; i < 8; i++) {
                int f = ltid + i * 128;
                int row = wc + (f >> 4), c = f & 15;
                cp16(kb + (row * KP2 + c * 4) * 4,
                     Kp + (long long)(t * 128 + row) * DH_ + c * 4);
            }
            #pragma unroll
            for (int i = 0; i < 8; i++) {
                int f = ltid + i * 128;
                int nrow = f >> 4;
                int ccol = wc + (f & 15) * 4;
                cp16(vb + (nrow * VTP + ccol) * 4,
                     VTp + (long long)nrow * TKV_ + t * 128 + ccol);
            }
            cp_commit();
        };

        // ---- stage Q (pre-rounded tf32) ----
        {
            uint32_t qbse = smaddr(sm);
            #pragma unroll
            for (int i = 0; i < 8; i++) {
                int f = tid + i * 256;
                int row = f >> 4, c = f & 15;
                cp16(qbse + (row * KP2 + c * 4) * 4,
                     Qp + (long long)(m0 + row) * DM_ + c * 4);
            }
            cp_commit();
            cp_wait<0>();
        }
        __syncthreads();
        uint32_t qf[8][2][4];
        #pragma unroll
        for (int kc = 0; kc < 8; kc++)
            #pragma unroll
            for (int mt = 0; mt < 2; mt++) {
                int rw = wr*32 + mt*16 + g;
                qf[kc][mt][0] = sm[(rw    ) * KP2 + kc*8 + tg    ];
                qf[kc][mt][1] = sm[(rw + 8) * KP2 + kc*8 + tg    ];
                qf[kc][mt][2] = sm[(rw    ) * KP2 + kc*8 + tg + 4];
                qf[kc][mt][3] = sm[(rw + 8) * KP2 + kc*8 + tg + 4];
            }
        __syncthreads();

        float rs[2][2];
        rs[0][0] = rs[0][1] = rs[1][0] = rs[1][1] = 0.f;
        float accO[2][8][4];
        #pragma unroll
        for (int mt = 0; mt < 2; mt++)
            #pragma unroll
            for (int nj = 0; nj < 8; nj++)
                #pragma unroll
                for (int r = 0; r < 4; r++) accO[mt][nj][r] = 0.f;

        issueHalf(0, 0);
        if (nT > 1) issueHalf(1, 1);

        for (int t = 0; t < nT; t++) {
            if (t < nT - 1) cp_wait<1>(); else cp_wait<0>();
            barg128(1 + grp);
            if (t + 2 < nT) issueHalf(t + 2, (t + 2) % 3);

            const int k0 = t * 128;
            const uint32_t* Ks = sm + (t % 3) * KBW;
            const uint32_t* Vs = sm + 3 * KBW + (t % 3) * VTW;
            const bool diag = (t == nT - 1);

            if (diag && wc >= wr * 32 + 32) {
                float2 z2 = make_float2(0.f, 0.f);
                #pragma unroll
                for (int mt = 0; mt < 2; mt++) {
                    int rw = m0 + wr*32 + mt*16 + g;
                    #pragma unroll
                    for (int ni = 0; ni < 8; ni++) {
                        int col = k0 + wc + ni*8 + 2*tg;
                        *reinterpret_cast<float2*>(Pp + (long long)rw       * TKV_ + col) = z2;
                        *reinterpret_cast<float2*>(Pp + (long long)(rw + 8) * TKV_ + col) = z2;
                    }
                }
                continue;
            }

            // --- QK^T ---
            float accS[2][8][4];
            #pragma unroll
            for (int mt = 0; mt < 2; mt++)
                #pragma unroll
                for (int ni = 0; ni < 8; ni++)
                    #pragma unroll
                    for (int r = 0; r < 4; r++) accS[mt][ni][r] = 0.f;
            #pragma unroll
            for (int kc = 0; kc < 8; kc++) {
                uint2 bp[8];
                #pragma unroll
                for (int ni = 0; ni < 8; ni++)
                    bp[ni] = *reinterpret_cast<const uint2*>(
                        &Ks[(wc + ni*8 + g) * KP2 + kc*8 + 2*tg]);
                #pragma unroll
                for (int mt = 0; mt < 2; mt++)
                    #pragma unroll
                    for (int ni = 0; ni < 8; ni++)
                        mma_tf32(accS[mt][ni],
                                 qf[kc][mt][0], qf[kc][mt][1], qf[kc][mt][2], qf[kc][mt][3],
                                 bp[ni].x, bp[ni].y);
            }

            // --- E = exp2(s*SC2), mask, rowsum, store ---
            #pragma unroll
            for (int mt = 0; mt < 2; mt++) {
                int rw = m0 + wr*32 + mt*16 + g;
                #pragma unroll
                for (int ni = 0; ni < 8; ni++) {
                    int col = k0 + wc + ni*8 + 2*tg;
                    float p0 = exp2f(accS[mt][ni][0]*SC2_);
                    float p1 = exp2f(accS[mt][ni][1]*SC2_);
                    float p2 = exp2f(accS[mt][ni][2]*SC2_);
                    float p3 = exp2f(accS[mt][ni][3]*SC2_);
                    if (diag) {
                        if (col     > rw    ) p0 = 0.f;
                        if (col + 1 > rw    ) p1 = 0.f;
                        if (col     > rw + 8) p2 = 0.f;
                        if (col + 1 > rw + 8) p3 = 0.f;
                    }
                    rs[mt][0] += p0 + p1;
                    rs[mt][1] += p2 + p3;
                    *reinterpret_cast<float2*>(Pp + (long long)rw       * TKV_ + col) = make_float2(p0, p1);
                    *reinterpret_cast<float2*>(Pp + (long long)(rw + 8) * TKV_ + col) = make_float2(p2, p3);
                    accS[mt][ni][0] = p0; accS[mt][ni][1] = p1;
                    accS[mt][ni][2] = p2; accS[mt][ni][3] = p3;
                }
            }

            // --- AV ---
            #pragma unroll
            for (int kc = 0; kc < 8; kc++) {
                uint32_t af[2][4];
                #pragma unroll
                for (int mt = 0; mt < 2; mt++) {
                    af[mt][0] = f2tf32(accS[mt][kc][0]);
                    af[mt][1] = f2tf32(accS[mt][kc][2]);
                    af[mt][2] = f2tf32(accS[mt][kc][1]);
                    af[mt][3] = f2tf32(accS[mt][kc][3]);
                }
                #pragma unroll
                for (int nj = 0; nj < 8; nj++) {
                    uint2 bv = *reinterpret_cast<const uint2*>(
                        &Vs[(nj*8 + g) * VTP + wc + kc*8 + 2*tg]);
                    #pragma unroll
                    for (int mt = 0; mt < 2; mt++)
                        mma_tf32(accO[mt][nj], af[mt][0], af[mt][1], af[mt][2], af[mt][3],
                                 bv.x, bv.y);
                }
            }
        }

        // ---- cross-group reduction ----
        #pragma unroll
        for (int mt = 0; mt < 2; mt++)
            #pragma unroll
            for (int p = 0; p < 2; p++) {
                float v = rs[mt][p];
                v += __shfl_xor_sync(0xffffffffu, v, 1);
                v += __shfl_xor_sync(0xffffffffu, v, 2);
                rs[mt][p] = v;
            }

        __syncthreads();
        float* redS = (float*)sm;
        float* redO = (float*)sm + 256;
        if (grp == 1) {
            #pragma unroll
            for (int mt = 0; mt < 2; mt++) {
                int lr = wr*32 + mt*16 + g;
                if (tg == 0) {
                    redS[lr]     = rs[mt][0];
                    redS[lr + 8] = rs[mt][1];
                }
                #pragma unroll
                for (int nj = 0; nj < 8; nj++) {
                    *reinterpret_cast<float2*>(&redO[(lr    ) * 64 + nj*8 + 2*tg]) =
                        make_float2(accO[mt][nj][0], accO[mt][nj][1]);
                    *reinterpret_cast<float2*>(&redO[(lr + 8) * 64 + nj*8 + 2*tg]) =
                        make_float2(accO[mt][nj][2], accO[mt][nj][3]);
                }
            }
        }
        __syncthreads();

        if (grp == 0) {
            #pragma unroll
            for (int mt = 0; mt < 2; mt++) {
                int lr = wr*32 + mt*16 + g;
                float s0 = rs[mt][0] + redS[lr];
                float s1 = rs[mt][1] + redS[lr + 8];
                const float inv0 = 1.0f / s0;
                const float inv1 = 1.0f / s1;
                int rw = m0 + lr;
                if (tg == 0) {
                    Invg[(long long)bh * TQ_ + rw]     = inv0;
                    Invg[(long long)bh * TQ_ + rw + 8] = inv1;
                }
                #pragma unroll
                for (int nj = 0; nj < 8; nj++) {
                    int col = nj*8 + 2*tg;
                    float2 r0 = *reinterpret_cast<float2*>(&redO[(lr    ) * 64 + col]);
                    float2 r1 = *reinterpret_cast<float2*>(&redO[(lr + 8) * 64 + col]);
                    *reinterpret_cast<float2*>(Op + (long long)rw       * DM_ + col) =
                        make_float2((accO[mt][nj][0] + r0.x) * inv0,
                                    (accO[mt][nj][1] + r0.y) * inv0);
                    *reinterpret_cast<float2*>(Op + (long long)(rw + 8) * DM_ + col) =
                        make_float2((accO[mt][nj][2] + r1.x) * inv1,
                                    (accO[mt][nj][3] + r1.y) * inv1);
                }
            }
        }
    }
}

// ===================== normalize P (causal half only) =====================
__global__ void __launch_bounds__(128) normalize_P(
    float* __restrict__ P, const float* __restrict__ Inv)
{
    const long long r = blockIdx.x;
    const int q = (int)(r & (TQ_ - 1));
    const float s = Inv[r];
    float4* p = reinterpret_cast<float4*>(P + r * TKV_);
    const int n4 = (q + 4) >> 2;
    for (int i = threadIdx.x; i < n4; i += 128) {
        float4 v = p[i];
        v.x *= s; v.y *= s; v.z *= s; v.w *= s;
        p[i] = v;
    }
}

// ===================== launch =====================
extern "C" void kernel_launch(void* const* d_in, const int* in_sizes, int n_in,
                              void* d_out, int out_size)
{
    const float* q  = (const float*)d_in[0];
    const float* kv = (const float*)d_in[1];
    const float* Wq = (const float*)d_in[3];
    const float* bq = (const float*)d_in[4];
    const float* Wk = (const float*)d_in[5];
    const float* bk = (const float*)d_in[6];
    const float* Wv = (const float*)d_in[7];
    const float* bv = (const float*)d_in[8];
    const float* Wo = (const float*)d_in[9];
    const float* bo = (const float*)d_in[10];
    float* out = (float*)d_out;
    (void)in_sizes; (void)n_in;

    float *gQ, *gK, *gVT, *gS, *gATT, *gINV;
    cudaGetSymbolAddress((void**)&gQ,   g_Q);
    cudaGetSymbolAddress((void**)&gK,   g_K);
    cudaGetSymbolAddress((void**)&gVT,  g_VT);
    cudaGetSymbolAddress((void**)&gS,   g_S);
    cudaGetSymbolAddress((void**)&gATT, g_ATT);
    cudaGetSymbolAddress((void**)&gINV, g_INV);

    float* attn_dst = (out_size >= OUT_ELEMS + ATT_ELEMS) ? (out + OUT_ELEMS) : gS;

    static cudaStream_t s1 = nullptr, s2 = nullptr;
    static cudaEvent_t e0 = nullptr, e1 = nullptr, e2 = nullptr, e3 = nullptr, ez = nullptr;
    static bool init_done = false;
    if (!init_done) {
        cudaFuncSetAttribute(proj_gemm,
            cudaFuncAttributeMaxDynamicSharedMemorySize, PROJ_SMEM);
        cudaFuncSetAttribute(kv_pipe,
            cudaFuncAttributeMaxDynamicSharedMemorySize, KVP_SMEM);
        cudaFuncSetAttribute(fused_attn,
            cudaFuncAttributeMaxDynamicSharedMemorySize, FA_SMEM_BYTES);
        cudaStreamCreateWithFlags(&s1, cudaStreamNonBlocking);
        cudaStreamCreateWithFlags(&s2, cudaStreamNonBlocking);
        cudaEventCreateWithFlags(&e0, cudaEventDisableTiming);
        cudaEventCreateWithFlags(&e1, cudaEventDisableTiming);
        cudaEventCreateWithFlags(&e2, cudaEventDisableTiming);
        cudaEventCreateWithFlags(&e3, cudaEventDisableTiming);
        cudaEventCreateWithFlags(&ez, cudaEventDisableTiming);
        init_done = true;
    }

    // fork: kv proj + counter reset on s1, zero-fill on s2, Q proj on main
    cudaEventRecord(e0, 0);
    cudaStreamWaitEvent(s1, e0, 0);
    cudaStreamWaitEvent(s2, e0, 0);
    reset_ctr<<<1, 1, 0, s1>>>();
    kv_pipe<<<dim3(1, (B_*TKV_)/128, 2), 128, KVP_SMEM, s1>>>(
        kv, Wk, Wv, bk, bv, gK, gVT);
    cudaEventRecord(e1, s1);
    zero_P<<<dim3(TQ_/128, B_*NH_), 256, 0, s2>>>(attn_dst);
    cudaEventRecord(ez, s2);

    proj_gemm<<<dim3(DM_/128, (B_*TQ_)/128), 256, PROJ_SMEM>>>(q, Wq, gQ, bq, 2);

    // join kv, then persistent fused attention on main
    cudaStreamWaitEvent(0, e1, 0);
    fused_attn<<<152, 256, FA_SMEM_BYTES>>>(
        gQ, gK, gVT, attn_dst, gATT, gINV);

    // fork: normalize on s1 overlaps final projection on main
    cudaEventRecord(e2, 0);
    cudaStreamWaitEvent(s1, e2, 0);
    normalize_P<<<B_*NH_*TQ_, 128, 0, s1>>>(attn_dst, gINV);
    cudaEventRecord(e3, s1);

    proj_gemm<<<dim3(DM_/128, (B_*TQ_)/128), 256, PROJ_SMEM>>>(gATT, Wo, out, bo, 0);
    cudaStreamWaitEvent(0, e3, 0);
    cudaStreamWaitEvent(0, ez, 0);
}

// round 16
// speedup vs baseline: 1.1458x; 1.0211x over previous
#include <cuda_runtime.h>
#include <cstdint>

#define B_   2
#define TQ_  2048
#define TKV_ 2048
#define DM_  1024
#define NH_  16
#define DH_  64
#define OUT_ELEMS (B_*TQ_*DM_)
#define ATT_ELEMS (B_*NH_*TQ_*TKV_)
#define SC2_ 0.18033688011112543f   /* 0.125 * log2(e) */

__device__ float g_Q[B_*TQ_*DM_];
__device__ float g_K[B_*TKV_*DH_];
__device__ float g_VT[B_*DH_*TKV_];
__device__ float g_S[ATT_ELEMS];
__device__ float g_ATT[B_*TQ_*DM_];
__device__ float g_INV[B_*NH_*TQ_];
__device__ int   g_WQ;               // persistent work counter

__device__ __forceinline__ uint32_t f2tf32(float f) {
    uint32_t u;
    asm("cvt.rna.tf32.f32 %0, %1;" : "=r"(u) : "f"(f));
    return u;
}
__device__ __forceinline__ uint32_t cvt_u(uint32_t w) {
    return f2tf32(__uint_as_float(w));
}
__device__ __forceinline__ uint32_t smaddr(const void* p) {
    return (uint32_t)__cvta_generic_to_shared(p);
}
__device__ __forceinline__ void cp16(uint32_t dst, const void* src) {
    asm volatile("cp.async.cg.shared.global [%0], [%1], 16;" :: "r"(dst), "l"(src));
}
__device__ __forceinline__ void cp_commit() {
    asm volatile("cp.async.commit_group;");
}
template<int N> __device__ __forceinline__ void cp_wait() {
    asm volatile("cp.async.wait_group %0;" :: "n"(N));
}
__device__ __forceinline__ void barg128(int id) {
    asm volatile("bar.sync %0, %1;" :: "r"(id), "r"(128) : "memory");
}

__device__ __forceinline__ void mma_tf32(float c[4],
    uint32_t a0, uint32_t a1, uint32_t a2, uint32_t a3,
    uint32_t b0, uint32_t b1)
{
    asm volatile(
        "mma.sync.aligned.m16n8k8.row.col.f32.tf32.tf32.f32 "
        "{%0,%1,%2,%3},{%4,%5,%6,%7},{%8,%9},{%0,%1,%2,%3};"
        : "+f"(c[0]), "+f"(c[1]), "+f"(c[2]), "+f"(c[3])
        : "r"(a0), "r"(a1), "r"(a2), "r"(a3), "r"(b0), "r"(b1));
}

// ===================== pipelined TF32 GEMM core (2-stage double buffer) =====================
#define PK 36

template<int BN, int NTHR>
__device__ __forceinline__ void gemm_core(
    uint32_t* sm, const float* A, int lda, const float* Bp, int ldb,
    float* C, int ldc, const float* bias, int m0, int n0, int epi)
{
    const int STW = (128 + BN) * PK;
    const int tid = threadIdx.x;
    const int warpId = tid >> 5, lane = tid & 31;
    const int warpM = warpId & 1, warpN = warpId >> 1;
    const int g = lane >> 2, tg = lane & 3;

    constexpr int ACH = 1024 / NTHR;
    constexpr int BCH = (BN * 8) / NTHR;

    auto issue = [&](int t, int s) {
        const float* Asrc = A + (long long)m0 * lda + t * 32;
        uint32_t abase = smaddr(sm + s * STW);
        #pragma unroll
        for (int i = 0; i < ACH; i++) {
            int f = tid + i * NTHR;
            int row = f >> 3, c = f & 7;
            cp16(abase + (row * PK + c * 4) * 4, Asrc + (long long)row * lda + c * 4);
        }
        const float* Bsrc = Bp + (long long)n0 * ldb + t * 32;
        uint32_t bbase = smaddr(sm + s * STW + 128 * PK);
        #pragma unroll
        for (int i = 0; i < BCH; i++) {
            int f = tid + i * NTHR;
            int row = f >> 3, c = f & 7;
            cp16(bbase + (row * PK + c * 4) * 4, Bsrc + (long long)row * ldb + c * 4);
        }
        cp_commit();
    };

    float acc[4][4][4];
    #pragma unroll
    for (int mi = 0; mi < 4; mi++)
        #pragma unroll
        for (int ni = 0; ni < 4; ni++)
            #pragma unroll
            for (int r = 0; r < 4; r++) acc[mi][ni][r] = 0.f;

    const int T = 1024 / 32;
    issue(0, 0);
    issue(1, 1);

    for (int t = 0; t < T; t++) {
        if (t < T - 1) cp_wait<1>(); else cp_wait<0>();
        __syncthreads();

        const uint32_t* As = sm + (t & 1) * STW;
        const uint32_t* Bs = As + 128 * PK;

        #pragma unroll
        for (int kk = 0; kk < 32; kk += 8) {
            uint32_t a[4][4], b[4][2];
            #pragma unroll
            for (int mi = 0; mi < 4; mi++) {
                int mB = warpM * 64 + mi * 16;
                a[mi][0] = cvt_u(As[(mB + g    ) * PK + kk + tg    ]);
                a[mi][1] = cvt_u(As[(mB + g + 8) * PK + kk + tg    ]);
                a[mi][2] = cvt_u(As[(mB + g    ) * PK + kk + tg + 4]);
                a[mi][3] = cvt_u(As[(mB + g + 8) * PK + kk + tg + 4]);
            }
            #pragma unroll
            for (int ni = 0; ni < 4; ni++) {
                int nB = warpN * 32 + ni * 8;
                b[ni][0] = cvt_u(Bs[(nB + g) * PK + kk + tg    ]);
                b[ni][1] = cvt_u(Bs[(nB + g) * PK + kk + tg + 4]);
            }
            #pragma unroll
            for (int mi = 0; mi < 4; mi++)
                #pragma unroll
                for (int ni = 0; ni < 4; ni++)
                    mma_tf32(acc[mi][ni], a[mi][0], a[mi][1], a[mi][2], a[mi][3],
                             b[ni][0], b[ni][1]);
        }
        __syncthreads();
        if (t + 2 < T) issue(t + 2, t & 1);
    }

    #pragma unroll
    for (int mi = 0; mi < 4; mi++) {
        #pragma unroll
        for (int ni = 0; ni < 4; ni++) {
            int m = m0 + warpM * 64 + mi * 16 + g;
            int n = n0 + warpN * 32 + ni * 8 + 2 * tg;
            float b0 = bias[n], b1 = bias[n + 1];
            float v00 = acc[mi][ni][0] + b0, v01 = acc[mi][ni][1] + b1;
            float v10 = acc[mi][ni][2] + b0, v11 = acc[mi][ni][3] + b1;
            if (epi == 0) {
                *reinterpret_cast<float2*>(C + (long long)m * ldc + n)       = make_float2(v00, v01);
                *reinterpret_cast<float2*>(C + (long long)(m + 8) * ldc + n) = make_float2(v10, v11);
            } else {
                float r00 = __uint_as_float(f2tf32(v00));
                float r01 = __uint_as_float(f2tf32(v01));
                float r10 = __uint_as_float(f2tf32(v10));
                float r11 = __uint_as_float(f2tf32(v11));
                if (epi == 1) {
                    int base = n & ~7;
                    int j0 = n & 7, j1 = j0 + 1;
                    int n0p = base + ((j0 < 4) ? 2*j0 : 2*j0 - 7);
                    int n1p = base + ((j1 < 4) ? 2*j1 : 2*j1 - 7);
                    C[(long long)m * ldc + n0p] = r00;
                    C[(long long)m * ldc + n1p] = r01;
                    C[(long long)(m + 8) * ldc + n0p] = r10;
                    C[(long long)(m + 8) * ldc + n1p] = r11;
                } else if (epi == 3) {
                    long long bb  = (long long)(m >> 11) * DH_ * TKV_;
                    int kv0 = m & (TKV_ - 1);
                    C[bb + (long long)n       * TKV_ + kv0    ] = r00;
                    C[bb + (long long)(n + 1) * TKV_ + kv0    ] = r01;
                    C[bb + (long long)n       * TKV_ + kv0 + 8] = r10;
                    C[bb + (long long)(n + 1) * TKV_ + kv0 + 8] = r11;
                } else {
                    *reinterpret_cast<float2*>(C + (long long)m * ldc + n)       = make_float2(r00, r01);
                    *reinterpret_cast<float2*>(C + (long long)(m + 8) * ldc + n) = make_float2(r10, r11);
                }
            }
        }
    }
}

#define PROJ_SMEM ((2*(128+128)*PK)*4)   // 73728 B -> 2 CTAs/SM
#define KVP_SMEM  ((2*(128+64)*PK)*4)    // 55296 B

__global__ void __launch_bounds__(256, 2) proj_gemm(
    const float* __restrict__ A, const float* __restrict__ Bp,
    float* __restrict__ C, const float* __restrict__ bias, int epi)
{
    extern __shared__ uint32_t sm[];
    gemm_core<128, 256>(sm, A, DM_, Bp, DM_, C, DM_, bias,
                        blockIdx.y * 128, blockIdx.x * 128, epi);
}

__global__ void __launch_bounds__(128) kv_pipe(
    const float* __restrict__ A,
    const float* __restrict__ Wk_, const float* __restrict__ Wv_,
    const float* __restrict__ bk_, const float* __restrict__ bv_,
    float* __restrict__ CK, float* __restrict__ CVT)
{
    extern __shared__ uint32_t sm[];
    const float* Bp   = blockIdx.z ? Wv_ : Wk_;
    const float* bias = blockIdx.z ? bv_ : bk_;
    float* C          = blockIdx.z ? CVT : CK;
    gemm_core<64, 128>(sm, A, DM_, Bp, DM_, C, DH_, bias,
                       blockIdx.y * 128, 0, blockIdx.z ? 3 : 1);
}

// ===================== zero upper-triangle of P =====================
__global__ void __launch_bounds__(256) zero_P(float* __restrict__ P)
{
    const int m0 = blockIdx.x * 128;
    float* Pp = P + (long long)blockIdx.y * TQ_ * TKV_;
    const int zc0 = m0 + 128;
    const int W = (TKV_ - zc0) >> 2;
    if (W <= 0) return;
    float4 z = make_float4(0.f, 0.f, 0.f, 0.f);
    for (int idx = threadIdx.x; idx < 128 * W; idx += 256) {
        int r = idx / W, c4 = idx - r * W;
        *reinterpret_cast<float4*>(Pp + (long long)(m0 + r) * TKV_ + zc0 + c4*4) = z;
    }
}

__global__ void reset_ctr() { g_WQ = 0; }

// ===================== Fused attention: persistent work-stealing CTAs =====================
#define KP2 72
#define VTP 136
#define KBW (128*KP2)
#define VTW (64*VTP)
#define FA_SMEM_BYTES ((3*KBW + 3*VTW)*4)   // 215040 B
#define NQB (TQ_/128)
#define NWORK (NQB * B_ * NH_)               // 512 work units

__global__ void __launch_bounds__(256, 1) fused_attn(
    const float* __restrict__ Qg, const float* __restrict__ Kg,
    const float* __restrict__ VTg, float* __restrict__ Pg,
    float* __restrict__ Og, float* __restrict__ Invg)
{
    extern __shared__ uint32_t sm[];
    __shared__ int s_w;

    const int tid = threadIdx.x;
    const int wid = tid >> 5;
    const int wr  = wid & 3;
    const int grp = wid >> 2;
    const int wc  = grp * 64;
    const int ltid = tid & 127;
    const int lane = tid & 31;
    const int g = lane >> 2, tg = lane & 3;

    for (;;) {
        __syncthreads();
        if (tid == 0) s_w = atomicAdd(&g_WQ, 1);
        __syncthreads();
        const int w = s_w;
        if (w >= NWORK) break;

        const int qb = NQB - 1 - (w >> 5);
        const int bh = w & 31;
        const int b  = bh >> 4, h = bh & 15;
        const int m0 = qb * 128;
        const int nT = qb + 1;

        const float* Qp  = Qg  + (long long)b * TQ_ * DM_ + h * DH_;
        const float* Kp  = Kg  + (long long)b * TKV_ * DH_;
        const float* VTp = VTg + (long long)b * DH_ * TKV_;
        float* Pp = Pg + (long long)bh * TQ_ * TKV_;
        float* Op = Og + (long long)b * TQ_ * DM_ + h * DH_;

        auto issueHalf = [&](int t, int s) {
            uint32_t kb = smaddr(sm + s * KBW);
            uint32_t vb = smaddr(sm + 3 * KBW + s * VTW);
            #pragma unroll
            for (int i = 0; i < 8; i++) {
                int f = ltid + i * 128;
                int row = wc + (f >> 4), c = f & 15;
                cp16(kb + (row * KP2 + c * 4) * 4,
                     Kp + (long long)(t * 128 + row) * DH_ + c * 4);
            }
            #pragma unroll
            for (int i = 0; i < 8; i++) {
                int f = ltid + i * 128;
                int nrow = f >> 4;
                int ccol = wc + (f & 15) * 4;
                cp16(vb + (nrow * VTP + ccol) * 4,
                     VTp + (long long)nrow * TKV_ + t * 128 + ccol);
            }
            cp_commit();
        };

        // ---- stage Q (pre-rounded tf32) ----
        {
            uint32_t qbse = smaddr(sm);
            #pragma unroll
            for (int i = 0; i < 8; i++) {
                int f = tid + i * 256;
                int row = f >> 4, c = f & 15;
                cp16(qbse + (row * KP2 + c * 4) * 4,
                     Qp + (long long)(m0 + row) * DM_ + c * 4);
            }
            cp_commit();
            cp_wait<0>();
        }
        __syncthreads();
        uint32_t qf[8][2][4];
        #pragma unroll
        for (int kc = 0; kc < 8; kc++)
            #pragma unroll
            for (int mt = 0; mt < 2; mt++) {
                int rw = wr*32 + mt*16 + g;
                qf[kc][mt][0] = sm[(rw    ) * KP2 + kc*8 + tg    ];
                qf[kc][mt][1] = sm[(rw + 8) * KP2 + kc*8 + tg    ];
                qf[kc][mt][2] = sm[(rw    ) * KP2 + kc*8 + tg + 4];
                qf[kc][mt][3] = sm[(rw + 8) * KP2 + kc*8 + tg + 4];
            }
        __syncthreads();

        float rs[2][2];
        rs[0][0] = rs[0][1] = rs[1][0] = rs[1][1] = 0.f;
        float accO[2][8][4];
        #pragma unroll
        for (int mt = 0; mt < 2; mt++)
            #pragma unroll
            for (int nj = 0; nj < 8; nj++)
                #pragma unroll
                for (int r = 0; r < 4; r++) accO[mt][nj][r] = 0.f;

        issueHalf(0, 0);
        if (nT > 1) issueHalf(1, 1);

        for (int t = 0; t < nT; t++) {
            if (t < nT - 1) cp_wait<1>(); else cp_wait<0>();
            barg128(1 + grp);
            if (t + 2 < nT) issueHalf(t + 2, (t + 2) % 3);

            const int k0 = t * 128;
            const uint32_t* Ks = sm + (t % 3) * KBW;
            const uint32_t* Vs = sm + 3 * KBW + (t % 3) * VTW;
            const bool diag = (t == nT - 1);

            if (diag && wc >= wr * 32 + 32) {
                float2 z2 = make_float2(0.f, 0.f);
                #pragma unroll
                for (int mt = 0; mt < 2; mt++) {
                    int rw = m0 + wr*32 + mt*16 + g;
                    #pragma unroll
                    for (int ni = 0; ni < 8; ni++) {
                        int col = k0 + wc + ni*8 + 2*tg;
                        *reinterpret_cast<float2*>(Pp + (long long)rw       * TKV_ + col) = z2;
                        *reinterpret_cast<float2*>(Pp + (long long)(rw + 8) * TKV_ + col) = z2;
                    }
                }
                continue;
            }

            // --- QK^T ---
            float accS[2][8][4];
            #pragma unroll
            for (int mt = 0; mt < 2; mt++)
                #pragma unroll
                for (int ni = 0; ni < 8; ni++)
                    #pragma unroll
                    for (int r = 0; r < 4; r++) accS[mt][ni][r] = 0.f;
            #pragma unroll
            for (int kc = 0; kc < 8; kc++) {
                uint2 bp[8];
                #pragma unroll
                for (int ni = 0; ni < 8; ni++)
                    bp[ni] = *reinterpret_cast<const uint2*>(
                        &Ks[(wc + ni*8 + g) * KP2 + kc*8 + 2*tg]);
                #pragma unroll
                for (int mt = 0; mt < 2; mt++)
                    #pragma unroll
                    for (int ni = 0; ni < 8; ni++)
                        mma_tf32(accS[mt][ni],
                                 qf[kc][mt][0], qf[kc][mt][1], qf[kc][mt][2], qf[kc][mt][3],
                                 bp[ni].x, bp[ni].y);
            }

            // --- E = exp2(s*SC2), mask, rowsum, store ---
            #pragma unroll
            for (int mt = 0; mt < 2; mt++) {
                int rw = m0 + wr*32 + mt*16 + g;
                #pragma unroll
                for (int ni = 0; ni < 8; ni++) {
                    int col = k0 + wc + ni*8 + 2*tg;
                    float p0 = exp2f(accS[mt][ni][0]*SC2_);
                    float p1 = exp2f(accS[mt][ni][1]*SC2_);
                    float p2 = exp2f(accS[mt][ni][2]*SC2_);
                    float p3 = exp2f(accS[mt][ni][3]*SC2_);
                    if (diag) {
                        if (col     > rw    ) p0 = 0.f;
                        if (col + 1 > rw    ) p1 = 0.f;
                        if (col     > rw + 8) p2 = 0.f;
                        if (col + 1 > rw + 8) p3 = 0.f;
                    }
                    rs[mt][0] += p0 + p1;
                    rs[mt][1] += p2 + p3;
                    *reinterpret_cast<float2*>(Pp + (long long)rw       * TKV_ + col) = make_float2(p0, p1);
                    *reinterpret_cast<float2*>(Pp + (long long)(rw + 8) * TKV_ + col) = make_float2(p2, p3);
                    accS[mt][ni][0] = p0; accS[mt][ni][1] = p1;
                    accS[mt][ni][2] = p2; accS[mt][ni][3] = p3;
                }
            }

            // --- AV ---
            #pragma unroll
            for (int kc = 0; kc < 8; kc++) {
                uint32_t af[2][4];
                #pragma unroll
                for (int mt = 0; mt < 2; mt++) {
                    af[mt][0] = f2tf32(accS[mt][kc][0]);
                    af[mt][1] = f2tf32(accS[mt][kc][2]);
                    af[mt][2] = f2tf32(accS[mt][kc][1]);
                    af[mt][3] = f2tf32(accS[mt][kc][3]);
                }
                #pragma unroll
                for (int nj = 0; nj < 8; nj++) {
                    uint2 bv = *reinterpret_cast<const uint2*>(
                        &Vs[(nj*8 + g) * VTP + wc + kc*8 + 2*tg]);
                    #pragma unroll
                    for (int mt = 0; mt < 2; mt++)
                        mma_tf32(accO[mt][nj], af[mt][0], af[mt][1], af[mt][2], af[mt][3],
                                 bv.x, bv.y);
                }
            }
        }

        // ---- cross-group reduction ----
        #pragma unroll
        for (int mt = 0; mt < 2; mt++)
            #pragma unroll
            for (int p = 0; p < 2; p++) {
                float v = rs[mt][p];
                v += __shfl_xor_sync(0xffffffffu, v, 1);
                v += __shfl_xor_sync(0xffffffffu, v, 2);
                rs[mt][p] = v;
            }

        __syncthreads();
        float* redS = (float*)sm;
        float* redO = (float*)sm + 256;
        if (grp == 1) {
            #pragma unroll
            for (int mt = 0; mt < 2; mt++) {
                int lr = wr*32 + mt*16 + g;
                if (tg == 0) {
                    redS[lr]     = rs[mt][0];
                    redS[lr + 8] = rs[mt][1];
                }
                #pragma unroll
                for (int nj = 0; nj < 8; nj++) {
                    *reinterpret_cast<float2*>(&redO[(lr    ) * 64 + nj*8 + 2*tg]) =
                        make_float2(accO[mt][nj][0], accO[mt][nj][1]);
                    *reinterpret_cast<float2*>(&redO[(lr + 8) * 64 + nj*8 + 2*tg]) =
                        make_float2(accO[mt][nj][2], accO[mt][nj][3]);
                }
            }
        }
        __syncthreads();

        if (grp == 0) {
            #pragma unroll
            for (int mt = 0; mt < 2; mt++) {
                int lr = wr*32 + mt*16 + g;
                float s0 = rs[mt][0] + redS[lr];
                float s1 = rs[mt][1] + redS[lr + 8];
                const float inv0 = 1.0f / s0;
                const float inv1 = 1.0f / s1;
                int rw = m0 + lr;
                if (tg == 0) {
                    Invg[(long long)bh * TQ_ + rw]     = inv0;
                    Invg[(long long)bh * TQ_ + rw + 8] = inv1;
                }
                #pragma unroll
                for (int nj = 0; nj < 8; nj++) {
                    int col = nj*8 + 2*tg;
                    float2 r0 = *reinterpret_cast<float2*>(&redO[(lr    ) * 64 + col]);
                    float2 r1 = *reinterpret_cast<float2*>(&redO[(lr + 8) * 64 + col]);
                    *reinterpret_cast<float2*>(Op + (long long)rw       * DM_ + col) =
                        make_float2((accO[mt][nj][0] + r0.x) * inv0,
                                    (accO[mt][nj][1] + r0.y) * inv0);
                    *reinterpret_cast<float2*>(Op + (long long)(rw + 8) * DM_ + col) =
                        make_float2((accO[mt][nj][2] + r1.x) * inv1,
                                    (accO[mt][nj][3] + r1.y) * inv1);
                }
            }
        }
    }
}

// ===================== normalize P (causal half, 4 rows/block) =====================
__global__ void __launch_bounds__(256) normalize_P(
    float* __restrict__ P, const float* __restrict__ Inv)
{
    const long long r0 = (long long)blockIdx.x * 4;
    #pragma unroll 1
    for (int j = 0; j < 4; j++) {
        const long long r = r0 + j;
        const int q = (int)(r & (TQ_ - 1));
        const float s = Inv[r];
        float4* p = reinterpret_cast<float4*>(P + r * TKV_);
        const int n4 = (q + 4) >> 2;
        for (int i = threadIdx.x; i < n4; i += 256) {
            float4 v = p[i];
            v.x *= s; v.y *= s; v.z *= s; v.w *= s;
            p[i] = v;
        }
    }
}

// ===================== launch =====================
extern "C" void kernel_launch(void* const* d_in, const int* in_sizes, int n_in,
                              void* d_out, int out_size)
{
    const float* q  = (const float*)d_in[0];
    const float* kv = (const float*)d_in[1];
    const float* Wq = (const float*)d_in[3];
    const float* bq = (const float*)d_in[4];
    const float* Wk = (const float*)d_in[5];
    const float* bk = (const float*)d_in[6];
    const float* Wv = (const float*)d_in[7];
    const float* bv = (const float*)d_in[8];
    const float* Wo = (const float*)d_in[9];
    const float* bo = (const float*)d_in[10];
    float* out = (float*)d_out;
    (void)in_sizes; (void)n_in;

    float *gQ, *gK, *gVT, *gS, *gATT, *gINV;
    cudaGetSymbolAddress((void**)&gQ,   g_Q);
    cudaGetSymbolAddress((void**)&gK,   g_K);
    cudaGetSymbolAddress((void**)&gVT,  g_VT);
    cudaGetSymbolAddress((void**)&gS,   g_S);
    cudaGetSymbolAddress((void**)&gATT, g_ATT);
    cudaGetSymbolAddress((void**)&gINV, g_INV);

    float* attn_dst = (out_size >= OUT_ELEMS + ATT_ELEMS) ? (out + OUT_ELEMS) : gS;

    static cudaStream_t s1 = nullptr, s2 = nullptr;
    static cudaEvent_t e0 = nullptr, e1 = nullptr, e2 = nullptr, e3 = nullptr, ez = nullptr;
    static bool init_done = false;
    if (!init_done) {
        cudaFuncSetAttribute(proj_gemm,
            cudaFuncAttributeMaxDynamicSharedMemorySize, PROJ_SMEM);
        cudaFuncSetAttribute(kv_pipe,
            cudaFuncAttributeMaxDynamicSharedMemorySize, KVP_SMEM);
        cudaFuncSetAttribute(fused_attn,
            cudaFuncAttributeMaxDynamicSharedMemorySize, FA_SMEM_BYTES);
        cudaStreamCreateWithFlags(&s1, cudaStreamNonBlocking);
        cudaStreamCreateWithFlags(&s2, cudaStreamNonBlocking);
        cudaEventCreateWithFlags(&e0, cudaEventDisableTiming);
        cudaEventCreateWithFlags(&e1, cudaEventDisableTiming);
        cudaEventCreateWithFlags(&e2, cudaEventDisableTiming);
        cudaEventCreateWithFlags(&e3, cudaEventDisableTiming);
        cudaEventCreateWithFlags(&ez, cudaEventDisableTiming);
        init_done = true;
    }

    // fork: kv proj + counter reset on s1, zero-fill on s2, Q proj on main
    cudaEventRecord(e0, 0);
    cudaStreamWaitEvent(s1, e0, 0);
    cudaStreamWaitEvent(s2, e0, 0);
    reset_ctr<<<1, 1, 0, s1>>>();
    kv_pipe<<<dim3(1, (B_*TKV_)/128, 2), 128, KVP_SMEM, s1>>>(
        kv, Wk, Wv, bk, bv, gK, gVT);
    cudaEventRecord(e1, s1);
    zero_P<<<dim3(TQ_/128, B_*NH_), 256, 0, s2>>>(attn_dst);
    cudaEventRecord(ez, s2);

    proj_gemm<<<dim3(DM_/128, (B_*TQ_)/128), 256, PROJ_SMEM>>>(q, Wq, gQ, bq, 2);

    // join kv, then persistent fused attention on main
    cudaStreamWaitEvent(0, e1, 0);
    fused_attn<<<152, 256, FA_SMEM_BYTES>>>(
        gQ, gK, gVT, attn_dst, gATT, gINV);

    // fork: normalize on s1 overlaps final projection on main
    cudaEventRecord(e2, 0);
    cudaStreamWaitEvent(s1, e2, 0);
    normalize_P<<<(B_*NH_*TQ_)/4, 256, 0, s1>>>(attn_dst, gINV);
    cudaEventRecord(e3, s1);

    proj_gemm<<<dim3(DM_/128, (B_*TQ_)/128), 256, PROJ_SMEM>>>(gATT, Wo, out, bo, 0);
    cudaStreamWaitEvent(0, e3, 0);
    cudaStreamWaitEvent(0, ez, 0);
}